// round 12
// baseline (speedup 1.0000x reference)
#include <cuda_runtime.h>
#include <cuda_bf16.h>
#include <cstdint>

#define BB 4
#define LL 128
#define RR 48
#define HH 768
#define DDIM 100
#define BL 512
#define WSZ (HH*HH)

#define O_FHS 0
#define O_FHE 512
#define O_FTS 1024
#define O_FTE 25600
#define O_BTS 50176
#define O_BTE 50688
#define O_BHS 51200
#define O_BHE 75776

// ---------------- scratch ----------------
__device__ __align__(16) float g_C[6 * BL * HH];
__device__ __align__(16) float g_brel[RR * HH];
__device__ __align__(16) float g_PRf[RR * HH];
__device__ __align__(16) float g_PRb[RR * HH];
__device__ __align__(16) float g_PGf[BB * HH];
__device__ __align__(16) float g_PGb[BB * HH];
__device__ __align__(16) float g_heads[4 * BL];
__device__ int             g_span[2][BB][3];
__device__ __align__(16) float g_v[2 * BB * LL * RR];
__device__ __align__(16) float g_ctx[2 * BB * RR * HH];
__device__ __align__(16) float g_dot[4 * BL];
__device__ __align__(16) float g_cdot[4 * BB * RR];

// prepped bf16 hi/lo data
__device__ __align__(16) __nv_bfloat16 g_Abf[7 * 24 * 2 * 4096];
__device__ __align__(16) __nv_bfloat16 g_Bbf[10 * 12 * 24 * 2 * 2048];

// ================= PTX helpers =================
__device__ __forceinline__ uint32_t smem_u32(const void* p) {
    uint32_t a;
    asm("{ .reg .u64 t; cvta.to.shared.u64 t, %1; cvt.u32.u64 %0, t; }" : "=r"(a) : "l"(p));
    return a;
}
__device__ __forceinline__ void cp16(uint32_t dst, const void* src) {
    asm volatile("cp.async.cg.shared.global [%0], [%1], 16;" :: "r"(dst), "l"(src) : "memory");
}
__device__ __forceinline__ void cp_commit() { asm volatile("cp.async.commit_group;" ::: "memory"); }
__device__ __forceinline__ void cp_wait1()  { asm volatile("cp.async.wait_group 1;" ::: "memory"); }
__device__ __forceinline__ void cp_wait0()  { asm volatile("cp.async.wait_group 0;" ::: "memory"); }
__device__ __forceinline__ void ldm_x4(uint32_t* r, uint32_t addr) {
    asm volatile("ldmatrix.sync.aligned.m8n8.x4.shared.b16 {%0,%1,%2,%3}, [%4];"
                 : "=r"(r[0]), "=r"(r[1]), "=r"(r[2]), "=r"(r[3]) : "r"(addr));
}
__device__ __forceinline__ void mma_bf16(float* d, const uint32_t* a, const uint32_t* b) {
    asm volatile("mma.sync.aligned.m16n8k16.row.col.f32.bf16.bf16.f32 "
                 "{%0,%1,%2,%3}, {%4,%5,%6,%7}, {%8,%9}, {%0,%1,%2,%3};"
                 : "+f"(d[0]), "+f"(d[1]), "+f"(d[2]), "+f"(d[3])
                 : "r"(a[0]), "r"(a[1]), "r"(a[2]), "r"(a[3]), "r"(b[0]), "r"(b[1]));
}

#define STG_BYTES 30720
#define MMA_SMEM_TOTAL (3 * STG_BYTES)

// ================= prepB: transpose + split weights (all 10 mats) =================
__global__ void __launch_bounds__(256) k_preB(const float* __restrict__ big_w) {
    __shared__ float sm[64][65];
    int bid = blockIdx.x;
    int tid = threadIdx.x;
    int jW = bid / 144; int rem = bid % 144;
    int nb = rem / 12, kg = rem % 12;
    const float* W = big_w + jW * WSZ + (kg * 64) * HH + nb * 64;
    for (int i = tid; i < 1024; i += 256) {
        int kr = i >> 4, c4 = (i & 15) << 2;
        float4 v = *(const float4*)(W + kr * HH + c4);
        sm[kr][c4 + 0] = v.x; sm[kr][c4 + 1] = v.y; sm[kr][c4 + 2] = v.z; sm[kr][c4 + 3] = v.w;
    }
    __syncthreads();
    for (int i = tid; i < 512; i += 256) {
        int n = i >> 3, g = i & 7;
        union { unsigned short s[8]; uint4 v; } hi, lo;
        #pragma unroll
        for (int j = 0; j < 8; j++) {
            float x = sm[g * 8 + j][n];
            __nv_bfloat16 h = __float2bfloat16(x);
            float rem2 = x - __bfloat162float(h);
            hi.s[j] = __bfloat16_as_ushort(h);
            lo.s[j] = __bfloat16_as_ushort(__float2bfloat16(rem2));
        }
        int kc = kg * 2 + (g >> 2), kk8 = (g & 3) << 3;
        __nv_bfloat16* base = g_Bbf + (size_t)(((jW * 12 + nb) * 24 + kc) * 2) * 2048;
        *(uint4*)(base + n * 32 + kk8) = hi.v;
        *(uint4*)(base + 2048 + n * 32 + kk8) = lo.v;
    }
}

// ================= preR: brel | heads =================
__global__ void __launch_bounds__(256) k_preR(const float* __restrict__ bt,
                                              const float* __restrict__ rW,
                                              const float* __restrict__ rb,
                                              const float* __restrict__ token,
                                              const float* __restrict__ fc_w,
                                              const float* __restrict__ fc_b,
                                              float* __restrict__ out) {
    __shared__ float sm[104];
    int bid = blockIdx.x;
    int tid = threadIdx.x;
    if (bid < 48) {
        int r = bid;
        for (int i = tid; i < DDIM; i += 256) sm[i] = bt[r * DDIM + i];
        __syncthreads();
        for (int c = tid; c < HH; c += 256) {
            float acc = rb[c];
            #pragma unroll 4
            for (int d = 0; d < DDIM; d++) acc = fmaf(sm[d], rW[d * HH + c], acc);
            g_brel[r * HH + c] = acc;
        }
    } else {
        int t = bid - 48;
        const float* tok = token + t * HH;
        float a0 = 0.f, a1 = 0.f, a2 = 0.f, a3 = 0.f;
        for (int h = tid; h < HH; h += 256) {
            float x = tok[h];
            a0 = fmaf(x, fc_w[0 * HH + h], a0);
            a1 = fmaf(x, fc_w[1 * HH + h], a1);
            a2 = fmaf(x, fc_w[4 * HH + h], a2);
            a3 = fmaf(x, fc_w[5 * HH + h], a3);
        }
        #pragma unroll
        for (int o = 16; o; o >>= 1) {
            a0 += __shfl_xor_sync(0xffffffffu, a0, o);
            a1 += __shfl_xor_sync(0xffffffffu, a1, o);
            a2 += __shfl_xor_sync(0xffffffffu, a2, o);
            a3 += __shfl_xor_sync(0xffffffffu, a3, o);
        }
        int w = tid >> 5, lane = tid & 31;
        if (lane == 0) { sm[w * 4 + 0] = a0; sm[w * 4 + 1] = a1; sm[w * 4 + 2] = a2; sm[w * 4 + 3] = a3; }
        __syncthreads();
        if (tid == 0) {
            float s0 = 0.f, s1 = 0.f, s2 = 0.f, s3 = 0.f;
            #pragma unroll
            for (int i = 0; i < 8; i++) { s0 += sm[i*4+0]; s1 += sm[i*4+1]; s2 += sm[i*4+2]; s3 += sm[i*4+3]; }
            s0 += fc_b[0]; s1 += fc_b[1]; s2 += fc_b[4]; s3 += fc_b[5];
            g_heads[t] = s0; g_heads[BL + t] = s1; g_heads[2 * BL + t] = s2; g_heads[3 * BL + t] = s3;
            out[O_FHS + t] = s0; out[O_FHE + t] = s1; out[O_BTS + t] = s2; out[O_BTE + t] = s3;
        }
    }
}

// ================= prepA + span =================
__global__ void k_prepA2(const float* __restrict__ token, const float* __restrict__ f_rel,
                         const float* __restrict__ h_gs) {
    int bid = blockIdx.x;
    if (bid == 336) {
        int w = threadIdx.x >> 5, lane = threadIdx.x & 31;
        if (w >= 8) return;
        int hd = w >> 2, b = w & 3;
        const float* sv = g_heads + hd * 2 * BL + b * LL;
        const float* ev = sv + BL;
        int sidx = 0, has = 0;
        #pragma unroll 1
        for (int c = 0; c < 4; c++) {
            unsigned m = __ballot_sync(0xffffffffu, sv[c * 32 + lane] > 0.f);
            if (m) { sidx = c * 32 + __ffs(m) - 1; has = 1; break; }
        }
        int eidx = sidx;
        #pragma unroll 1
        for (int c = 0; c < 4; c++) {
            int p = c * 32 + lane;
            unsigned m = __ballot_sync(0xffffffffu, (ev[p] > 0.f) && (p >= sidx));
            if (m) { eidx = c * 32 + __ffs(m) - 1; break; }
        }
        if (lane == 0) {
            g_span[hd][b][0] = sidx;
            g_span[hd][b][1] = eidx - sidx + 1;
            g_span[hd][b][2] = has;
        }
        return;
    }
    int idx = bid * 256 + threadIdx.x;
    int g = idx % 96, r = idx / 96;
    int mt = r >> 7, trow = r & 127;
    const float* src = nullptr;
    bool valid = false;
    if (mt < 4)       { src = token + (mt * 128 + trow) * HH; valid = true; }
    else if (mt == 4) { valid = trow < RR; src = f_rel + trow * HH; }
    else if (mt == 5) { valid = trow < RR; src = g_brel + trow * HH; }
    else              { valid = trow < BB; src = h_gs + trow * HH; }
    float xs[8];
    if (valid) {
        float4 v0 = *(const float4*)(src + g * 8);
        float4 v1 = *(const float4*)(src + g * 8 + 4);
        xs[0] = v0.x; xs[1] = v0.y; xs[2] = v0.z; xs[3] = v0.w;
        xs[4] = v1.x; xs[5] = v1.y; xs[6] = v1.z; xs[7] = v1.w;
    } else {
        #pragma unroll
        for (int i = 0; i < 8; i++) xs[i] = 0.f;
    }
    union { unsigned short s[8]; uint4 v; } hi, lo;
    #pragma unroll
    for (int i = 0; i < 8; i++) {
        __nv_bfloat16 h = __float2bfloat16(xs[i]);
        float rem = xs[i] - __bfloat162float(h);
        hi.s[i] = __bfloat16_as_ushort(h);
        lo.s[i] = __bfloat16_as_ushort(__float2bfloat16(rem));
    }
    int kc = g >> 2, kk8 = (g & 3) << 3;
    __nv_bfloat16* bHi = g_Abf + ((mt * 24 + kc) * 2 + 0) * 4096 + trow * 32 + kk8;
    __nv_bfloat16* bLo = g_Abf + ((mt * 24 + kc) * 2 + 1) * 4096 + trow * 32 + kk8;
    *(uint4*)bHi = hi.v;
    *(uint4*)bLo = lo.v;
}

// ---------------- mma.sync bf16 GEMM: 128x64 tile, 3-stage pipeline, 1 sync/iter ----------------
__global__ void __launch_bounds__(256) k_mma(const float* __restrict__ big_b) {
    extern __shared__ char smem[];
    uint32_t sb = smem_u32(smem);
    int tid = threadIdx.x, wid = tid >> 5, lane = tid & 31;
    int wm = wid & 3, wn = wid >> 2;
    int bid = blockIdx.x;

    int jW, mt, nb, Mvalid; float* outp;
    if (bid < 288) {
        const int widx[6] = {0, 1, 4, 7, 8, 9};
        int j = bid / 48, rem = bid % 48;
        int mb = rem / 12; nb = rem % 12;
        jW = widx[j]; mt = mb; Mvalid = 128;
        outp = g_C + j * BL * HH + mb * 128 * HH;
    } else {
        int s = (bid - 288) / 12; nb = (bid - 288) % 12;
        const int wsel[4] = {2, 5, 3, 6};
        jW = wsel[s];
        if (s == 0)      { mt = 4; Mvalid = RR; outp = g_PRf; }
        else if (s == 1) { mt = 5; Mvalid = RR; outp = g_PRb; }
        else if (s == 2) { mt = 6; Mvalid = BB; outp = g_PGf; }
        else             { mt = 6; Mvalid = BB; outp = g_PGb; }
    }

    const char* gA = (const char*)(g_Abf + (size_t)(mt * 24) * 2 * 4096);
    const char* gB = (const char*)(g_Bbf + (size_t)((jW * 12 + nb) * 24) * 2 * 2048);

    auto stage = [&](int buf, int kc) {
        uint32_t dbase = sb + buf * STG_BYTES;
        const char* aSrc = gA + (size_t)kc * 2 * 8192;
        const char* bSrc = gB + (size_t)kc * 2 * 4096;
        #pragma unroll
        for (int ii = 0; ii < 6; ii++) {
            int i = tid + ii * 256;
            if (i < 1024) {
                int row = i >> 3, half = (i >> 2) & 1, c = i & 3;
                cp16(dbase + half * 10240 + row * 80 + c * 16,
                     aSrc + half * 8192 + row * 64 + c * 16);
            } else {
                int j2 = i - 1024;
                int row = j2 >> 3, half = (j2 >> 2) & 1, c = j2 & 3;
                cp16(dbase + 20480 + half * 5120 + row * 80 + c * 16,
                     bSrc + half * 4096 + row * 64 + c * 16);
            }
        }
    };

    float acc[2][4][4];
    #pragma unroll
    for (int a = 0; a < 2; a++)
        #pragma unroll
        for (int b = 0; b < 4; b++)
            #pragma unroll
            for (int c = 0; c < 4; c++) acc[a][b][c] = 0.f;

    uint32_t aOff = (uint32_t)((wm * 32 + (lane & 15)) * 80 + ((lane >> 4) * 8) * 2);
    uint32_t bOff = (uint32_t)((wn * 32 + (((lane >> 4) << 3) | (lane & 7))) * 80 + (lane & 8) * 2);

    // prologue: stages 0,1 in flight
    stage(0, 0); cp_commit();
    stage(1, 1); cp_commit();

    int buf = 0;
    for (int kc = 0; kc < 24; kc++) {
        if (kc + 1 < 24) cp_wait1();   // chunk kc landed (kc+1 still in flight)
        else             cp_wait0();
        __syncthreads();               // all warps see chunk kc; all done reading buf[(kc-1)%3]
        if (kc + 2 < 24) {             // overwrites buf[(kc-1)%3] — safe after sync
            stage((kc + 2) % 3, kc + 2);
            cp_commit();
        }

        uint32_t Ab = sb + buf * STG_BYTES;
        uint32_t Bb = Ab + 20480;
        #pragma unroll
        for (int k16 = 0; k16 < 2; k16++) {
            uint32_t ah[2][4], al[2][4], bh[2][4], blr[2][4];
            #pragma unroll
            for (int m = 0; m < 2; m++) {
                uint32_t ad = Ab + aOff + m * (16 * 80) + k16 * 32;
                ldm_x4(ah[m], ad);
                ldm_x4(al[m], ad + 10240);
            }
            #pragma unroll
            for (int nt = 0; nt < 2; nt++) {
                uint32_t bd = Bb + bOff + nt * (16 * 80) + k16 * 32;
                ldm_x4(bh[nt], bd);
                ldm_x4(blr[nt], bd + 5120);
            }
            #pragma unroll
            for (int m = 0; m < 2; m++) {
                #pragma unroll
                for (int j2 = 0; j2 < 4; j2++) {
                    const uint32_t* bhp = &bh[j2 >> 1][(j2 & 1) * 2];
                    const uint32_t* blp = &blr[j2 >> 1][(j2 & 1) * 2];
                    mma_bf16(acc[m][j2], ah[m], bhp);
                    mma_bf16(acc[m][j2], ah[m], blp);
                    mma_bf16(acc[m][j2], al[m], bhp);
                }
            }
        }
        buf = (buf == 2) ? 0 : buf + 1;
    }

    int lr = lane >> 2, lc = (lane & 3) * 2;
    #pragma unroll
    for (int m = 0; m < 2; m++) {
        #pragma unroll
        for (int j2 = 0; j2 < 4; j2++) {
            int col = nb * 64 + wn * 32 + j2 * 8 + lc;
            float2 bv = *(const float2*)(big_b + jW * HH + col);
            int row = wm * 32 + m * 16 + lr;
            if (row < Mvalid) {
                float2 o = make_float2(acc[m][j2][0] + bv.x, acc[m][j2][1] + bv.y);
                *(float2*)(outp + row * HH + col) = o;
            }
            if (row + 8 < Mvalid) {
                float2 o = make_float2(acc[m][j2][2] + bv.x, acc[m][j2][3] + bv.y);
                *(float2*)(outp + (row + 8) * HH + col) = o;
            }
        }
    }
}

// ---------------- attention scores (verified 125us version) ----------------
__global__ void __launch_bounds__(256) k_attn(const float* __restrict__ fc_w) {
    __shared__ __align__(16) float XS[8][HH];    // exp(2*(x+g))
    __shared__ __align__(16) float PRS[8][HH];   // exp(2*r)
    int bid = blockIdx.x;
    int hd = bid / 384; int rem = bid % 384;
    int b = rem / 96; rem %= 96;
    int lt = rem / 6, rt = rem % 6;
    const float* X  = g_C + (size_t)(2 + hd) * BL * HH + (b * LL + lt * 8) * HH;
    const float* PG = (hd ? g_PGb : g_PGf) + b * HH;
    const float* PR = (hd ? g_PRb : g_PRf) + rt * 8 * HH;
    int tid = threadIdx.x;
    for (int i = tid; i < 8 * HH / 4; i += 256) {
        int row = i / 192, c4 = (i % 192) << 2;
        float4 x = *(const float4*)(X + row * HH + c4);
        float4 g = *(const float4*)(PG + c4);
        x.x = __expf(2.0f * (x.x + g.x)); x.y = __expf(2.0f * (x.y + g.y));
        x.z = __expf(2.0f * (x.z + g.z)); x.w = __expf(2.0f * (x.w + g.w));
        *(float4*)&XS[row][c4] = x;
        float4 p = *(const float4*)(PR + row * HH + c4);
        p.x = __expf(2.0f * p.x); p.y = __expf(2.0f * p.y);
        p.z = __expf(2.0f * p.z); p.w = __expf(2.0f * p.w);
        *(float4*)&PRS[row][c4] = p;
    }
    __syncthreads();
    int w = tid >> 5, lane = tid & 31;
    float vw[24], xr[24];
    const float* Vw = fc_w + 8 * HH;
    #pragma unroll
    for (int j = 0; j < 24; j++) {
        int h = lane + (j << 5);
        vw[j] = Vw[h];
        xr[j] = XS[w][h];
    }
    float* vout = g_v + ((hd * BB + b) * LL + lt * 8 + w) * RR + rt * 8;
    #pragma unroll 2
    for (int r = 0; r < 8; r++) {
        float acc = 0.f;
        #pragma unroll
        for (int j = 0; j < 24; j++) {
            float v = xr[j] * PRS[r][lane + (j << 5)];
            float e = 1.0f - __fdividef(2.0f, v + 1.0f);
            acc = fmaf(e, vw[j], acc);
        }
        #pragma unroll
        for (int o = 16; o; o >>= 1) acc += __shfl_xor_sync(0xffffffffu, acc, o);
        if (lane == 0) vout[r] = acc;
    }
}

// ---------------- context with in-kernel softmax ----------------
__global__ void __launch_bounds__(128) k_ctx(const float* __restrict__ token) {
    __shared__ __align__(16) float As[LL][24];
    __shared__ float cmax[24], cinv[24];
    int bid = blockIdx.x;
    int hd = bid / 48; int rem = bid % 48;
    int b = rem / 12; int rem2 = rem % 12;
    int hc = rem2 / 2, rh = rem2 % 2;
    const float* Ag = g_v + (hd * BB + b) * LL * RR + rh * 24;
    int tid = threadIdx.x;
    for (int i = tid; i < LL * 6; i += 128) {
        int row = i / 6, c4 = (i % 6) << 2;
        *(float4*)&As[row][c4] = *(const float4*)(Ag + row * RR + c4);
    }
    __syncthreads();
    if (tid < 96) {
        int col = tid >> 2, q = tid & 3;
        float m = -1e30f;
        for (int l = q; l < LL; l += 4) m = fmaxf(m, As[l][col]);
        m = fmaxf(m, __shfl_xor_sync(0xffffffffu, m, 1));
        m = fmaxf(m, __shfl_xor_sync(0xffffffffu, m, 2));
        float s = 0.f;
        for (int l = q; l < LL; l += 4) s += __expf(As[l][col] - m);
        s += __shfl_xor_sync(0xffffffffu, s, 1);
        s += __shfl_xor_sync(0xffffffffu, s, 2);
        if (q == 0) { cmax[col] = m; cinv[col] = 1.0f / s; }
    }
    __syncthreads();
    for (int i = tid; i < LL * 24; i += 128) {
        int l = i / 24, c = i % 24;
        As[l][c] = __expf(As[l][c] - cmax[c]) * cinv[c];
    }
    __syncthreads();
    int h = hc * 128 + tid;
    const float* tok = token + b * LL * HH + h;
    float acc[24];
    #pragma unroll
    for (int r = 0; r < 24; r++) acc[r] = 0.f;
    for (int l = 0; l < LL; l++) {
        float t = tok[l * HH];
        #pragma unroll
        for (int r = 0; r < 24; r += 4) {
            float4 a = *(const float4*)&As[l][r];
            acc[r + 0] = fmaf(a.x, t, acc[r + 0]);
            acc[r + 1] = fmaf(a.y, t, acc[r + 1]);
            acc[r + 2] = fmaf(a.z, t, acc[r + 2]);
            acc[r + 3] = fmaf(a.w, t, acc[r + 3]);
        }
    }
    float* Cp = g_ctx + ((hd * BB + b) * RR + rh * 24) * HH + h;
    #pragma unroll
    for (int r = 0; r < 24; r++) Cp[r * HH] = acc[r];
}

// ---------------- fused hik | cdot ----------------
__global__ void __launch_bounds__(128) k_hikcdot(const float* __restrict__ token,
                                                 const float* __restrict__ fc_w) {
    int bid = blockIdx.x;
    int tid = threadIdx.x;
    if (bid < 512) {
        int t = bid;
        int b = t >> 7, l = t & 127;
        int sf = g_span[0][b][0], lenf = g_span[0][b][1], hasf = g_span[0][b][2];
        int sb2 = g_span[1][b][0], lenb = g_span[1][b][1], hasb = g_span[1][b][2];
        bool mf = hasf && (l < lenf);
        bool mb2 = hasb && (l < lenb);
        int rf = min(sf + l, LL - 1), rb = min(sb2 + l, LL - 1);
        const float* T0  = g_C + (b * LL + rf) * HH;
        const float* T1  = g_C + 1 * BL * HH + (b * LL + rb) * HH;
        const float* X8  = g_C + 4 * BL * HH + t * HH;
        const float* X9  = g_C + 5 * BL * HH + t * HH;
        const float* tok = token + t * HH;
        const float* w2 = fc_w + 2 * HH; const float* w3 = fc_w + 3 * HH;
        const float* w6 = fc_w + 6 * HH; const float* w7 = fc_w + 7 * HH;
        float a0 = 0.f, a1 = 0.f, a2 = 0.f, a3 = 0.f;
        for (int h = tid; h < HH; h += 128) {
            float vf = (mf ? T0[h] : 0.f) + X8[h] + tok[h];
            float vb = (mb2 ? T1[h] : 0.f) + X9[h] + tok[h];
            a0 = fmaf(vf, w2[h], a0); a1 = fmaf(vf, w3[h], a1);
            a2 = fmaf(vb, w6[h], a2); a3 = fmaf(vb, w7[h], a3);
        }
        #pragma unroll
        for (int o = 16; o; o >>= 1) {
            a0 += __shfl_xor_sync(0xffffffffu, a0, o);
            a1 += __shfl_xor_sync(0xffffffffu, a1, o);
            a2 += __shfl_xor_sync(0xffffffffu, a2, o);
            a3 += __shfl_xor_sync(0xffffffffu, a3, o);
        }
        __shared__ float red[4][4];
        int w = tid >> 5, lane = tid & 31;
        if (lane == 0) { red[w][0] = a0; red[w][1] = a1; red[w][2] = a2; red[w][3] = a3; }
        __syncthreads();
        if (tid == 0) {
            g_dot[t]          = red[0][0] + red[1][0] + red[2][0] + red[3][0];
            g_dot[BL + t]     = red[0][1] + red[1][1] + red[2][1] + red[3][1];
            g_dot[2 * BL + t] = red[0][2] + red[1][2] + red[2][2] + red[3][2];
            g_dot[3 * BL + t] = red[0][3] + red[1][3] + red[2][3] + red[3][3];
        }
    } else {
        int g = (bid - 512) * 4 + (tid >> 5);
        int lane = tid & 31;
        int hd = g / (BB * RR); int rem = g % (BB * RR);
        int b = rem / RR, r = rem % RR;
        const float* C  = g_ctx + ((hd * BB + b) * RR + r) * HH;
        const float* ws = fc_w + (hd ? 6 : 2) * HH;
        const float* we = fc_w + (hd ? 7 : 3) * HH;
        float as = 0.f, ae = 0.f;
        #pragma unroll
        for (int j = 0; j < 24; j++) {
            int h = lane + (j << 5);
            float c = C[h];
            as = fmaf(c, ws[h], as);
            ae = fmaf(c, we[h], ae);
        }
        #pragma unroll
        for (int o = 16; o; o >>= 1) {
            as += __shfl_xor_sync(0xffffffffu, as, o);
            ae += __shfl_xor_sync(0xffffffffu, ae, o);
        }
        if (lane == 0) {
            g_cdot[(hd * 2 + 0) * BB * RR + b * RR + r] = as;
            g_cdot[(hd * 2 + 1) * BB * RR + b * RR + r] = ae;
        }
    }
}

// ---------------- final broadcast logits ----------------
__global__ void k_final(float* __restrict__ out, const float* __restrict__ fc_b) {
    int idx = blockIdx.x * 256 + threadIdx.x;
    int head = idx / (BB * LL * RR), rem = idx % (BB * LL * RR);
    int b = rem / (LL * RR); int rem2 = rem % (LL * RR);
    int l = rem2 / RR, r = rem2 % RR;
    const int ooff[4] = {O_FTS, O_FTE, O_BHS, O_BHE};
    const int bsel[4] = {2, 3, 6, 7};
    float val = g_dot[head * BL + b * LL + l]
              + g_cdot[head * BB * RR + b * RR + r]
              + fc_b[bsel[head]];
    out[ooff[head] + rem] = val;
}

extern "C" void kernel_launch(void* const* d_in, const int* in_sizes, int n_in,
                              void* d_out, int out_size) {
    const float* h_gs       = (const float*)d_in[0];
    const float* token_embs = (const float*)d_in[1];
    const float* f_rel_embs = (const float*)d_in[2];
    const float* b_rel_tr   = (const float*)d_in[3];
    const float* r_proj_w   = (const float*)d_in[4];
    const float* r_proj_b   = (const float*)d_in[5];
    const float* fc_w       = (const float*)d_in[6];
    const float* fc_b       = (const float*)d_in[7];
    const float* big_w      = (const float*)d_in[8];
    const float* big_b      = (const float*)d_in[9];
    float* out = (float*)d_out;

    static int smem_set = 0;
    if (!smem_set) {
        cudaFuncSetAttribute(k_mma, cudaFuncAttributeMaxDynamicSharedMemorySize, MMA_SMEM_TOTAL);
        smem_set = 1;
    }

    k_preB<<<1440, 256>>>(big_w);                                              // slot 0
    k_preR<<<560, 256>>>(b_rel_tr, r_proj_w, r_proj_b, token_embs, fc_w, fc_b, out); // slot 1
    k_prepA2<<<337, 256>>>(token_embs, f_rel_embs, h_gs);                      // slot 2
    k_mma<<<336, 256, MMA_SMEM_TOTAL>>>(big_b);                                // slot 3 (profiled)
    k_attn<<<768, 256>>>(fc_w);
    k_ctx<<<96, 128>>>(token_embs);
    k_hikcdot<<<608, 128>>>(token_embs, fc_w);
    k_final<<<384, 256>>>(out, fc_b);
}

// round 13
// speedup vs baseline: 1.0032x; 1.0032x over previous
#include <cuda_runtime.h>
#include <cuda_bf16.h>
#include <cstdint>

#define BB 4
#define LL 128
#define RR 48
#define HH 768
#define DDIM 100
#define BL 512
#define WSZ (HH*HH)

#define O_FHS 0
#define O_FHE 512
#define O_FTS 1024
#define O_FTE 25600
#define O_BTS 50176
#define O_BTE 50688
#define O_BHS 51200
#define O_BHE 75776

// ---------------- scratch ----------------
__device__ __align__(16) float g_C[6 * BL * HH];
__device__ __align__(16) float g_brel[RR * HH];
__device__ __align__(16) float g_PRf[RR * HH];
__device__ __align__(16) float g_PRb[RR * HH];
__device__ __align__(16) float g_PGf[BB * HH];
__device__ __align__(16) float g_PGb[BB * HH];
__device__ __align__(16) float g_heads[4 * BL];
__device__ int             g_span[2][BB][3];
__device__ __align__(16) float g_v[2 * BB * LL * RR];
__device__ __align__(16) float g_ctx[2 * BB * RR * HH];
__device__ __align__(16) float g_dot[4 * BL];
__device__ __align__(16) float g_cdot[4 * BB * RR];

// prepped bf16 hi/lo data
__device__ __align__(16) __nv_bfloat16 g_Abf[7 * 24 * 2 * 4096];
__device__ __align__(16) __nv_bfloat16 g_Bbf[10 * 12 * 24 * 2 * 2048];

// ================= PTX helpers =================
__device__ __forceinline__ uint32_t smem_u32(const void* p) {
    uint32_t a;
    asm("{ .reg .u64 t; cvta.to.shared.u64 t, %1; cvt.u32.u64 %0, t; }" : "=r"(a) : "l"(p));
    return a;
}
__device__ __forceinline__ void cp16(uint32_t dst, const void* src) {
    asm volatile("cp.async.cg.shared.global [%0], [%1], 16;" :: "r"(dst), "l"(src) : "memory");
}
__device__ __forceinline__ void cp_commit() { asm volatile("cp.async.commit_group;" ::: "memory"); }
__device__ __forceinline__ void cp_wait1()  { asm volatile("cp.async.wait_group 1;" ::: "memory"); }
__device__ __forceinline__ void cp_wait0()  { asm volatile("cp.async.wait_group 0;" ::: "memory"); }
__device__ __forceinline__ void ldm_x4(uint32_t* r, uint32_t addr) {
    asm volatile("ldmatrix.sync.aligned.m8n8.x4.shared.b16 {%0,%1,%2,%3}, [%4];"
                 : "=r"(r[0]), "=r"(r[1]), "=r"(r[2]), "=r"(r[3]) : "r"(addr));
}
__device__ __forceinline__ void mma_bf16(float* d, const uint32_t* a, const uint32_t* b) {
    asm volatile("mma.sync.aligned.m16n8k16.row.col.f32.bf16.bf16.f32 "
                 "{%0,%1,%2,%3}, {%4,%5,%6,%7}, {%8,%9}, {%0,%1,%2,%3};"
                 : "+f"(d[0]), "+f"(d[1]), "+f"(d[2]), "+f"(d[3])
                 : "r"(a[0]), "r"(a[1]), "r"(a[2]), "r"(a[3]), "r"(b[0]), "r"(b[1]));
}

#define MMA_SMEM_TOTAL 61440

// ================= prepB: transpose + split weights (all 10 mats) =================
__global__ void __launch_bounds__(256) k_preB(const float* __restrict__ big_w) {
    __shared__ float sm[64][65];
    int bid = blockIdx.x;
    int tid = threadIdx.x;
    int jW = bid / 144; int rem = bid % 144;
    int nb = rem / 12, kg = rem % 12;
    const float* W = big_w + jW * WSZ + (kg * 64) * HH + nb * 64;
    for (int i = tid; i < 1024; i += 256) {
        int kr = i >> 4, c4 = (i & 15) << 2;
        float4 v = *(const float4*)(W + kr * HH + c4);
        sm[kr][c4 + 0] = v.x; sm[kr][c4 + 1] = v.y; sm[kr][c4 + 2] = v.z; sm[kr][c4 + 3] = v.w;
    }
    __syncthreads();
    for (int i = tid; i < 512; i += 256) {
        int n = i >> 3, g = i & 7;
        union { unsigned short s[8]; uint4 v; } hi, lo;
        #pragma unroll
        for (int j = 0; j < 8; j++) {
            float x = sm[g * 8 + j][n];
            __nv_bfloat16 h = __float2bfloat16(x);
            float rem2 = x - __bfloat162float(h);
            hi.s[j] = __bfloat16_as_ushort(h);
            lo.s[j] = __bfloat16_as_ushort(__float2bfloat16(rem2));
        }
        int kc = kg * 2 + (g >> 2), kk8 = (g & 3) << 3;
        __nv_bfloat16* base = g_Bbf + (size_t)(((jW * 12 + nb) * 24 + kc) * 2) * 2048;
        *(uint4*)(base + n * 32 + kk8) = hi.v;
        *(uint4*)(base + 2048 + n * 32 + kk8) = lo.v;
    }
}

// ================= preR: brel | heads =================
__global__ void __launch_bounds__(256) k_preR(const float* __restrict__ bt,
                                              const float* __restrict__ rW,
                                              const float* __restrict__ rb,
                                              const float* __restrict__ token,
                                              const float* __restrict__ fc_w,
                                              const float* __restrict__ fc_b,
                                              float* __restrict__ out) {
    __shared__ float sm[104];
    int bid = blockIdx.x;
    int tid = threadIdx.x;
    if (bid < 48) {
        int r = bid;
        for (int i = tid; i < DDIM; i += 256) sm[i] = bt[r * DDIM + i];
        __syncthreads();
        for (int c = tid; c < HH; c += 256) {
            float acc = rb[c];
            #pragma unroll 4
            for (int d = 0; d < DDIM; d++) acc = fmaf(sm[d], rW[d * HH + c], acc);
            g_brel[r * HH + c] = acc;
        }
    } else {
        int t = bid - 48;
        const float* tok = token + t * HH;
        float a0 = 0.f, a1 = 0.f, a2 = 0.f, a3 = 0.f;
        for (int h = tid; h < HH; h += 256) {
            float x = tok[h];
            a0 = fmaf(x, fc_w[0 * HH + h], a0);
            a1 = fmaf(x, fc_w[1 * HH + h], a1);
            a2 = fmaf(x, fc_w[4 * HH + h], a2);
            a3 = fmaf(x, fc_w[5 * HH + h], a3);
        }
        #pragma unroll
        for (int o = 16; o; o >>= 1) {
            a0 += __shfl_xor_sync(0xffffffffu, a0, o);
            a1 += __shfl_xor_sync(0xffffffffu, a1, o);
            a2 += __shfl_xor_sync(0xffffffffu, a2, o);
            a3 += __shfl_xor_sync(0xffffffffu, a3, o);
        }
        int w = tid >> 5, lane = tid & 31;
        if (lane == 0) { sm[w * 4 + 0] = a0; sm[w * 4 + 1] = a1; sm[w * 4 + 2] = a2; sm[w * 4 + 3] = a3; }
        __syncthreads();
        if (tid == 0) {
            float s0 = 0.f, s1 = 0.f, s2 = 0.f, s3 = 0.f;
            #pragma unroll
            for (int i = 0; i < 8; i++) { s0 += sm[i*4+0]; s1 += sm[i*4+1]; s2 += sm[i*4+2]; s3 += sm[i*4+3]; }
            s0 += fc_b[0]; s1 += fc_b[1]; s2 += fc_b[4]; s3 += fc_b[5];
            g_heads[t] = s0; g_heads[BL + t] = s1; g_heads[2 * BL + t] = s2; g_heads[3 * BL + t] = s3;
            out[O_FHS + t] = s0; out[O_FHE + t] = s1; out[O_BTS + t] = s2; out[O_BTE + t] = s3;
        }
    }
}

// ================= prepA + span =================
__global__ void k_prepA2(const float* __restrict__ token, const float* __restrict__ f_rel,
                         const float* __restrict__ h_gs) {
    int bid = blockIdx.x;
    if (bid == 336) {
        int w = threadIdx.x >> 5, lane = threadIdx.x & 31;
        if (w >= 8) return;
        int hd = w >> 2, b = w & 3;
        const float* sv = g_heads + hd * 2 * BL + b * LL;
        const float* ev = sv + BL;
        int sidx = 0, has = 0;
        #pragma unroll 1
        for (int c = 0; c < 4; c++) {
            unsigned m = __ballot_sync(0xffffffffu, sv[c * 32 + lane] > 0.f);
            if (m) { sidx = c * 32 + __ffs(m) - 1; has = 1; break; }
        }
        int eidx = sidx;
        #pragma unroll 1
        for (int c = 0; c < 4; c++) {
            int p = c * 32 + lane;
            unsigned m = __ballot_sync(0xffffffffu, (ev[p] > 0.f) && (p >= sidx));
            if (m) { eidx = c * 32 + __ffs(m) - 1; break; }
        }
        if (lane == 0) {
            g_span[hd][b][0] = sidx;
            g_span[hd][b][1] = eidx - sidx + 1;
            g_span[hd][b][2] = has;
        }
        return;
    }
    int idx = bid * 256 + threadIdx.x;
    int g = idx % 96, r = idx / 96;
    int mt = r >> 7, trow = r & 127;
    const float* src = nullptr;
    bool valid = false;
    if (mt < 4)       { src = token + (mt * 128 + trow) * HH; valid = true; }
    else if (mt == 4) { valid = trow < RR; src = f_rel + trow * HH; }
    else if (mt == 5) { valid = trow < RR; src = g_brel + trow * HH; }
    else              { valid = trow < BB; src = h_gs + trow * HH; }
    float xs[8];
    if (valid) {
        float4 v0 = *(const float4*)(src + g * 8);
        float4 v1 = *(const float4*)(src + g * 8 + 4);
        xs[0] = v0.x; xs[1] = v0.y; xs[2] = v0.z; xs[3] = v0.w;
        xs[4] = v1.x; xs[5] = v1.y; xs[6] = v1.z; xs[7] = v1.w;
    } else {
        #pragma unroll
        for (int i = 0; i < 8; i++) xs[i] = 0.f;
    }
    union { unsigned short s[8]; uint4 v; } hi, lo;
    #pragma unroll
    for (int i = 0; i < 8; i++) {
        __nv_bfloat16 h = __float2bfloat16(xs[i]);
        float rem = xs[i] - __bfloat162float(h);
        hi.s[i] = __bfloat16_as_ushort(h);
        lo.s[i] = __bfloat16_as_ushort(__float2bfloat16(rem));
    }
    int kc = g >> 2, kk8 = (g & 3) << 3;
    __nv_bfloat16* bHi = g_Abf + ((mt * 24 + kc) * 2 + 0) * 4096 + trow * 32 + kk8;
    __nv_bfloat16* bLo = g_Abf + ((mt * 24 + kc) * 2 + 1) * 4096 + trow * 32 + kk8;
    *(uint4*)bHi = hi.v;
    *(uint4*)bLo = lo.v;
}

// ---------------- mma.sync bf16 GEMM: 128x64, 2-stage, split accumulators ----------------
__global__ void __launch_bounds__(256) k_mma(const float* __restrict__ big_b) {
    extern __shared__ char smem[];
    uint32_t sb = smem_u32(smem);
    int tid = threadIdx.x, wid = tid >> 5, lane = tid & 31;
    int wm = wid & 3, wn = wid >> 2;
    int bid = blockIdx.x;

    int jW, mt, nb, Mvalid; float* outp;
    if (bid < 288) {
        const int widx[6] = {0, 1, 4, 7, 8, 9};
        int j = bid / 48, rem = bid % 48;
        int mb = rem / 12; nb = rem % 12;
        jW = widx[j]; mt = mb; Mvalid = 128;
        outp = g_C + j * BL * HH + mb * 128 * HH;
    } else {
        int s = (bid - 288) / 12; nb = (bid - 288) % 12;
        const int wsel[4] = {2, 5, 3, 6};
        jW = wsel[s];
        if (s == 0)      { mt = 4; Mvalid = RR; outp = g_PRf; }
        else if (s == 1) { mt = 5; Mvalid = RR; outp = g_PRb; }
        else if (s == 2) { mt = 6; Mvalid = BB; outp = g_PGf; }
        else             { mt = 6; Mvalid = BB; outp = g_PGb; }
    }

    const char* gA = (const char*)(g_Abf + (size_t)(mt * 24) * 2 * 4096);
    const char* gB = (const char*)(g_Bbf + (size_t)((jW * 12 + nb) * 24) * 2 * 2048);

    auto stage = [&](int buf, int kc) {
        uint32_t dbase = sb + buf * 30720;
        const char* aSrc = gA + (size_t)kc * 2 * 8192;
        const char* bSrc = gB + (size_t)kc * 2 * 4096;
        #pragma unroll
        for (int ii = 0; ii < 6; ii++) {
            int i = tid + ii * 256;
            if (i < 1024) {
                int row = i >> 3, half = (i >> 2) & 1, c = i & 3;
                cp16(dbase + half * 10240 + row * 80 + c * 16,
                     aSrc + half * 8192 + row * 64 + c * 16);
            } else {
                int j2 = i - 1024;
                int row = j2 >> 3, half = (j2 >> 2) & 1, c = j2 & 3;
                cp16(dbase + 20480 + half * 5120 + row * 80 + c * 16,
                     bSrc + half * 4096 + row * 64 + c * 16);
            }
        }
    };

    float accP[2][4][4], accQ[2][4][4];
    #pragma unroll
    for (int a = 0; a < 2; a++)
        #pragma unroll
        for (int b = 0; b < 4; b++)
            #pragma unroll
            for (int c = 0; c < 4; c++) { accP[a][b][c] = 0.f; accQ[a][b][c] = 0.f; }

    uint32_t aOff = (uint32_t)((wm * 32 + (lane & 15)) * 80 + ((lane >> 4) * 8) * 2);
    uint32_t bOff = (uint32_t)((wn * 32 + (((lane >> 4) << 3) | (lane & 7))) * 80 + (lane & 8) * 2);

    stage(0, 0);
    cp_commit();

    for (int kc = 0; kc < 24; kc++) {
        int buf = kc & 1;
        if (kc + 1 < 24) { stage(buf ^ 1, kc + 1); cp_commit(); cp_wait1(); }
        else             { cp_wait0(); }
        __syncthreads();

        uint32_t Ab = sb + buf * 30720;
        uint32_t Bb = Ab + 20480;
        #pragma unroll
        for (int k16 = 0; k16 < 2; k16++) {
            uint32_t ah[2][4], al[2][4], bh[2][4], blr[2][4];
            #pragma unroll
            for (int m = 0; m < 2; m++) {
                uint32_t ad = Ab + aOff + m * (16 * 80) + k16 * 32;
                ldm_x4(ah[m], ad);
                ldm_x4(al[m], ad + 10240);
            }
            #pragma unroll
            for (int nt = 0; nt < 2; nt++) {
                uint32_t bd = Bb + bOff + nt * (16 * 80) + k16 * 32;
                ldm_x4(bh[nt], bd);
                ldm_x4(blr[nt], bd + 5120);
            }
            #pragma unroll
            for (int m = 0; m < 2; m++) {
                #pragma unroll
                for (int j2 = 0; j2 < 4; j2++) {
                    const uint32_t* bhp = &bh[j2 >> 1][(j2 & 1) * 2];
                    const uint32_t* blp = &blr[j2 >> 1][(j2 & 1) * 2];
                    mma_bf16(accP[m][j2], ah[m], bhp);   // chain P (independent)
                    mma_bf16(accQ[m][j2], ah[m], blp);   // chain Q
                    mma_bf16(accQ[m][j2], al[m], bhp);
                }
            }
        }
        __syncthreads();
    }

    int lr = lane >> 2, lc = (lane & 3) * 2;
    #pragma unroll
    for (int m = 0; m < 2; m++) {
        #pragma unroll
        for (int j2 = 0; j2 < 4; j2++) {
            int col = nb * 64 + wn * 32 + j2 * 8 + lc;
            float2 bv = *(const float2*)(big_b + jW * HH + col);
            int row = wm * 32 + m * 16 + lr;
            if (row < Mvalid) {
                float2 o = make_float2(accP[m][j2][0] + accQ[m][j2][0] + bv.x,
                                       accP[m][j2][1] + accQ[m][j2][1] + bv.y);
                *(float2*)(outp + row * HH + col) = o;
            }
            if (row + 8 < Mvalid) {
                float2 o = make_float2(accP[m][j2][2] + accQ[m][j2][2] + bv.x,
                                       accP[m][j2][3] + accQ[m][j2][3] + bv.y);
                *(float2*)(outp + (row + 8) * HH + col) = o;
            }
        }
    }
}

// ---------------- attention scores (verified 125us version) ----------------
__global__ void __launch_bounds__(256) k_attn(const float* __restrict__ fc_w) {
    __shared__ __align__(16) float XS[8][HH];
    __shared__ __align__(16) float PRS[8][HH];
    int bid = blockIdx.x;
    int hd = bid / 384; int rem = bid % 384;
    int b = rem / 96; rem %= 96;
    int lt = rem / 6, rt = rem % 6;
    const float* X  = g_C + (size_t)(2 + hd) * BL * HH + (b * LL + lt * 8) * HH;
    const float* PG = (hd ? g_PGb : g_PGf) + b * HH;
    const float* PR = (hd ? g_PRb : g_PRf) + rt * 8 * HH;
    int tid = threadIdx.x;
    for (int i = tid; i < 8 * HH / 4; i += 256) {
        int row = i / 192, c4 = (i % 192) << 2;
        float4 x = *(const float4*)(X + row * HH + c4);
        float4 g = *(const float4*)(PG + c4);
        x.x = __expf(2.0f * (x.x + g.x)); x.y = __expf(2.0f * (x.y + g.y));
        x.z = __expf(2.0f * (x.z + g.z)); x.w = __expf(2.0f * (x.w + g.w));
        *(float4*)&XS[row][c4] = x;
        float4 p = *(const float4*)(PR + row * HH + c4);
        p.x = __expf(2.0f * p.x); p.y = __expf(2.0f * p.y);
        p.z = __expf(2.0f * p.z); p.w = __expf(2.0f * p.w);
        *(float4*)&PRS[row][c4] = p;
    }
    __syncthreads();
    int w = tid >> 5, lane = tid & 31;
    float vw[24], xr[24];
    const float* Vw = fc_w + 8 * HH;
    #pragma unroll
    for (int j = 0; j < 24; j++) {
        int h = lane + (j << 5);
        vw[j] = Vw[h];
        xr[j] = XS[w][h];
    }
    float* vout = g_v + ((hd * BB + b) * LL + lt * 8 + w) * RR + rt * 8;
    #pragma unroll 2
    for (int r = 0; r < 8; r++) {
        float acc = 0.f;
        #pragma unroll
        for (int j = 0; j < 24; j++) {
            float v = xr[j] * PRS[r][lane + (j << 5)];
            float e = 1.0f - __fdividef(2.0f, v + 1.0f);
            acc = fmaf(e, vw[j], acc);
        }
        #pragma unroll
        for (int o = 16; o; o >>= 1) acc += __shfl_xor_sync(0xffffffffu, acc, o);
        if (lane == 0) vout[r] = acc;
    }
}

// ---------------- context with in-kernel softmax ----------------
__global__ void __launch_bounds__(128) k_ctx(const float* __restrict__ token) {
    __shared__ __align__(16) float As[LL][24];
    __shared__ float cmax[24], cinv[24];
    int bid = blockIdx.x;
    int hd = bid / 48; int rem = bid % 48;
    int b = rem / 12; int rem2 = rem % 12;
    int hc = rem2 / 2, rh = rem2 % 2;
    const float* Ag = g_v + (hd * BB + b) * LL * RR + rh * 24;
    int tid = threadIdx.x;
    for (int i = tid; i < LL * 6; i += 128) {
        int row = i / 6, c4 = (i % 6) << 2;
        *(float4*)&As[row][c4] = *(const float4*)(Ag + row * RR + c4);
    }
    __syncthreads();
    if (tid < 96) {
        int col = tid >> 2, q = tid & 3;
        float m = -1e30f;
        for (int l = q; l < LL; l += 4) m = fmaxf(m, As[l][col]);
        m = fmaxf(m, __shfl_xor_sync(0xffffffffu, m, 1));
        m = fmaxf(m, __shfl_xor_sync(0xffffffffu, m, 2));
        float s = 0.f;
        for (int l = q; l < LL; l += 4) s += __expf(As[l][col] - m);
        s += __shfl_xor_sync(0xffffffffu, s, 1);
        s += __shfl_xor_sync(0xffffffffu, s, 2);
        if (q == 0) { cmax[col] = m; cinv[col] = 1.0f / s; }
    }
    __syncthreads();
    for (int i = tid; i < LL * 24; i += 128) {
        int l = i / 24, c = i % 24;
        As[l][c] = __expf(As[l][c] - cmax[c]) * cinv[c];
    }
    __syncthreads();
    int h = hc * 128 + tid;
    const float* tok = token + b * LL * HH + h;
    float acc[24];
    #pragma unroll
    for (int r = 0; r < 24; r++) acc[r] = 0.f;
    for (int l = 0; l < LL; l++) {
        float t = tok[l * HH];
        #pragma unroll
        for (int r = 0; r < 24; r += 4) {
            float4 a = *(const float4*)&As[l][r];
            acc[r + 0] = fmaf(a.x, t, acc[r + 0]);
            acc[r + 1] = fmaf(a.y, t, acc[r + 1]);
            acc[r + 2] = fmaf(a.z, t, acc[r + 2]);
            acc[r + 3] = fmaf(a.w, t, acc[r + 3]);
        }
    }
    float* Cp = g_ctx + ((hd * BB + b) * RR + rh * 24) * HH + h;
    #pragma unroll
    for (int r = 0; r < 24; r++) Cp[r * HH] = acc[r];
}

// ---------------- fused hik | cdot ----------------
__global__ void __launch_bounds__(128) k_hikcdot(const float* __restrict__ token,
                                                 const float* __restrict__ fc_w) {
    int bid = blockIdx.x;
    int tid = threadIdx.x;
    if (bid < 512) {
        int t = bid;
        int b = t >> 7, l = t & 127;
        int sf = g_span[0][b][0], lenf = g_span[0][b][1], hasf = g_span[0][b][2];
        int sb2 = g_span[1][b][0], lenb = g_span[1][b][1], hasb = g_span[1][b][2];
        bool mf = hasf && (l < lenf);
        bool mb2 = hasb && (l < lenb);
        int rf = min(sf + l, LL - 1), rb = min(sb2 + l, LL - 1);
        const float* T0  = g_C + (b * LL + rf) * HH;
        const float* T1  = g_C + 1 * BL * HH + (b * LL + rb) * HH;
        const float* X8  = g_C + 4 * BL * HH + t * HH;
        const float* X9  = g_C + 5 * BL * HH + t * HH;
        const float* tok = token + t * HH;
        const float* w2 = fc_w + 2 * HH; const float* w3 = fc_w + 3 * HH;
        const float* w6 = fc_w + 6 * HH; const float* w7 = fc_w + 7 * HH;
        float a0 = 0.f, a1 = 0.f, a2 = 0.f, a3 = 0.f;
        for (int h = tid; h < HH; h += 128) {
            float vf = (mf ? T0[h] : 0.f) + X8[h] + tok[h];
            float vb = (mb2 ? T1[h] : 0.f) + X9[h] + tok[h];
            a0 = fmaf(vf, w2[h], a0); a1 = fmaf(vf, w3[h], a1);
            a2 = fmaf(vb, w6[h], a2); a3 = fmaf(vb, w7[h], a3);
        }
        #pragma unroll
        for (int o = 16; o; o >>= 1) {
            a0 += __shfl_xor_sync(0xffffffffu, a0, o);
            a1 += __shfl_xor_sync(0xffffffffu, a1, o);
            a2 += __shfl_xor_sync(0xffffffffu, a2, o);
            a3 += __shfl_xor_sync(0xffffffffu, a3, o);
        }
        __shared__ float red[4][4];
        int w = tid >> 5, lane = tid & 31;
        if (lane == 0) { red[w][0] = a0; red[w][1] = a1; red[w][2] = a2; red[w][3] = a3; }
        __syncthreads();
        if (tid == 0) {
            g_dot[t]          = red[0][0] + red[1][0] + red[2][0] + red[3][0];
            g_dot[BL + t]     = red[0][1] + red[1][1] + red[2][1] + red[3][1];
            g_dot[2 * BL + t] = red[0][2] + red[1][2] + red[2][2] + red[3][2];
            g_dot[3 * BL + t] = red[0][3] + red[1][3] + red[2][3] + red[3][3];
        }
    } else {
        int g = (bid - 512) * 4 + (tid >> 5);
        int lane = tid & 31;
        int hd = g / (BB * RR); int rem = g % (BB * RR);
        int b = rem / RR, r = rem % RR;
        const float* C  = g_ctx + ((hd * BB + b) * RR + r) * HH;
        const float* ws = fc_w + (hd ? 6 : 2) * HH;
        const float* we = fc_w + (hd ? 7 : 3) * HH;
        float as = 0.f, ae = 0.f;
        #pragma unroll
        for (int j = 0; j < 24; j++) {
            int h = lane + (j << 5);
            float c = C[h];
            as = fmaf(c, ws[h], as);
            ae = fmaf(c, we[h], ae);
        }
        #pragma unroll
        for (int o = 16; o; o >>= 1) {
            as += __shfl_xor_sync(0xffffffffu, as, o);
            ae += __shfl_xor_sync(0xffffffffu, ae, o);
        }
        if (lane == 0) {
            g_cdot[(hd * 2 + 0) * BB * RR + b * RR + r] = as;
            g_cdot[(hd * 2 + 1) * BB * RR + b * RR + r] = ae;
        }
    }
}

// ---------------- final broadcast logits ----------------
__global__ void k_final(float* __restrict__ out, const float* __restrict__ fc_b) {
    int idx = blockIdx.x * 256 + threadIdx.x;
    int head = idx / (BB * LL * RR), rem = idx % (BB * LL * RR);
    int b = rem / (LL * RR); int rem2 = rem % (LL * RR);
    int l = rem2 / RR, r = rem2 % RR;
    const int ooff[4] = {O_FTS, O_FTE, O_BHS, O_BHE};
    const int bsel[4] = {2, 3, 6, 7};
    float val = g_dot[head * BL + b * LL + l]
              + g_cdot[head * BB * RR + b * RR + r]
              + fc_b[bsel[head]];
    out[ooff[head] + rem] = val;
}

extern "C" void kernel_launch(void* const* d_in, const int* in_sizes, int n_in,
                              void* d_out, int out_size) {
    const float* h_gs       = (const float*)d_in[0];
    const float* token_embs = (const float*)d_in[1];
    const float* f_rel_embs = (const float*)d_in[2];
    const float* b_rel_tr   = (const float*)d_in[3];
    const float* r_proj_w   = (const float*)d_in[4];
    const float* r_proj_b   = (const float*)d_in[5];
    const float* fc_w       = (const float*)d_in[6];
    const float* fc_b       = (const float*)d_in[7];
    const float* big_w      = (const float*)d_in[8];
    const float* big_b      = (const float*)d_in[9];
    float* out = (float*)d_out;

    static int smem_set = 0;
    if (!smem_set) {
        cudaFuncSetAttribute(k_mma, cudaFuncAttributeMaxDynamicSharedMemorySize, MMA_SMEM_TOTAL);
        smem_set = 1;
    }

    k_preB<<<1440, 256>>>(big_w);                                              // slot 0
    k_preR<<<560, 256>>>(b_rel_tr, r_proj_w, r_proj_b, token_embs, fc_w, fc_b, out); // slot 1
    k_prepA2<<<337, 256>>>(token_embs, f_rel_embs, h_gs);                      // slot 2
    k_mma<<<336, 256, MMA_SMEM_TOTAL>>>(big_b);                                // slot 3 (profiled)
    k_attn<<<768, 256>>>(fc_w);
    k_ctx<<<96, 128>>>(token_embs);
    k_hikcdot<<<608, 128>>>(token_embs, fc_w);
    k_final<<<384, 256>>>(out, fc_b);
}

// round 14
// speedup vs baseline: 1.0464x; 1.0431x over previous
#include <cuda_runtime.h>
#include <cuda_bf16.h>
#include <cstdint>

#define BB 4
#define LL 128
#define RR 48
#define HH 768
#define DDIM 100
#define BL 512
#define WSZ (HH*HH)

#define O_FHS 0
#define O_FHE 512
#define O_FTS 1024
#define O_FTE 25600
#define O_BTS 50176
#define O_BTE 50688
#define O_BHS 51200
#define O_BHE 75776

// ---------------- scratch ----------------
__device__ __align__(16) float g_C[6 * BL * HH];
__device__ __align__(16) float g_brel[RR * HH];
__device__ __align__(16) float g_PRf[RR * HH];
__device__ __align__(16) float g_PRb[RR * HH];
__device__ __align__(16) float g_PGf[BB * HH];
__device__ __align__(16) float g_PGb[BB * HH];
__device__ __align__(16) float g_heads[4 * BL];
__device__ int             g_span[2][BB][3];
__device__ __align__(16) float g_v[2 * BB * LL * RR];
__device__ __align__(16) float g_ctx[2 * BB * RR * HH];
__device__ __align__(16) float g_dot[4 * BL];
__device__ __align__(16) float g_cdot[4 * BB * RR];

// prepped bf16 hi/lo data
__device__ __align__(16) __nv_bfloat16 g_Abf[7 * 24 * 2 * 4096];
__device__ __align__(16) __nv_bfloat16 g_Bbf[10 * 12 * 24 * 2 * 2048];

// ================= PTX helpers =================
__device__ __forceinline__ uint32_t smem_u32(const void* p) {
    uint32_t a;
    asm("{ .reg .u64 t; cvta.to.shared.u64 t, %1; cvt.u32.u64 %0, t; }" : "=r"(a) : "l"(p));
    return a;
}
__device__ __forceinline__ void cp16(uint32_t dst, const void* src) {
    asm volatile("cp.async.cg.shared.global [%0], [%1], 16;" :: "r"(dst), "l"(src) : "memory");
}
__device__ __forceinline__ void cp_commit() { asm volatile("cp.async.commit_group;" ::: "memory"); }
__device__ __forceinline__ void cp_wait1()  { asm volatile("cp.async.wait_group 1;" ::: "memory"); }
__device__ __forceinline__ void cp_wait0()  { asm volatile("cp.async.wait_group 0;" ::: "memory"); }
__device__ __forceinline__ void ldm_x4(uint32_t* r, uint32_t addr) {
    asm volatile("ldmatrix.sync.aligned.m8n8.x4.shared.b16 {%0,%1,%2,%3}, [%4];"
                 : "=r"(r[0]), "=r"(r[1]), "=r"(r[2]), "=r"(r[3]) : "r"(addr));
}
__device__ __forceinline__ void mma_bf16(float* d, const uint32_t* a, const uint32_t* b) {
    asm volatile("mma.sync.aligned.m16n8k16.row.col.f32.bf16.bf16.f32 "
                 "{%0,%1,%2,%3}, {%4,%5,%6,%7}, {%8,%9}, {%0,%1,%2,%3};"
                 : "+f"(d[0]), "+f"(d[1]), "+f"(d[2]), "+f"(d[3])
                 : "r"(a[0]), "r"(a[1]), "r"(a[2]), "r"(a[3]), "r"(b[0]), "r"(b[1]));
}

#define MMA_SMEM_TOTAL 61440

// ================= prepB: transpose + split weights (all 10 mats) =================
__global__ void __launch_bounds__(256) k_preB(const float* __restrict__ big_w) {
    __shared__ float sm[64][65];
    int bid = blockIdx.x;
    int tid = threadIdx.x;
    int jW = bid / 144; int rem = bid % 144;
    int nb = rem / 12, kg = rem % 12;
    const float* W = big_w + jW * WSZ + (kg * 64) * HH + nb * 64;
    for (int i = tid; i < 1024; i += 256) {
        int kr = i >> 4, c4 = (i & 15) << 2;
        float4 v = *(const float4*)(W + kr * HH + c4);
        sm[kr][c4 + 0] = v.x; sm[kr][c4 + 1] = v.y; sm[kr][c4 + 2] = v.z; sm[kr][c4 + 3] = v.w;
    }
    __syncthreads();
    for (int i = tid; i < 512; i += 256) {
        int n = i >> 3, g = i & 7;
        union { unsigned short s[8]; uint4 v; } hi, lo;
        #pragma unroll
        for (int j = 0; j < 8; j++) {
            float x = sm[g * 8 + j][n];
            __nv_bfloat16 h = __float2bfloat16(x);
            float rem2 = x - __bfloat162float(h);
            hi.s[j] = __bfloat16_as_ushort(h);
            lo.s[j] = __bfloat16_as_ushort(__float2bfloat16(rem2));
        }
        int kc = kg * 2 + (g >> 2), kk8 = (g & 3) << 3;
        __nv_bfloat16* base = g_Bbf + (size_t)(((jW * 12 + nb) * 24 + kc) * 2) * 2048;
        *(uint4*)(base + n * 32 + kk8) = hi.v;
        *(uint4*)(base + 2048 + n * 32 + kk8) = lo.v;
    }
}

// ================= preR: brel | heads =================
__global__ void __launch_bounds__(256) k_preR(const float* __restrict__ bt,
                                              const float* __restrict__ rW,
                                              const float* __restrict__ rb,
                                              const float* __restrict__ token,
                                              const float* __restrict__ fc_w,
                                              const float* __restrict__ fc_b,
                                              float* __restrict__ out) {
    __shared__ float sm[104];
    int bid = blockIdx.x;
    int tid = threadIdx.x;
    if (bid < 48) {
        int r = bid;
        for (int i = tid; i < DDIM; i += 256) sm[i] = bt[r * DDIM + i];
        __syncthreads();
        for (int c = tid; c < HH; c += 256) {
            float acc = rb[c];
            #pragma unroll 4
            for (int d = 0; d < DDIM; d++) acc = fmaf(sm[d], rW[d * HH + c], acc);
            g_brel[r * HH + c] = acc;
        }
    } else {
        int t = bid - 48;
        const float* tok = token + t * HH;
        float a0 = 0.f, a1 = 0.f, a2 = 0.f, a3 = 0.f;
        for (int h = tid; h < HH; h += 256) {
            float x = tok[h];
            a0 = fmaf(x, fc_w[0 * HH + h], a0);
            a1 = fmaf(x, fc_w[1 * HH + h], a1);
            a2 = fmaf(x, fc_w[4 * HH + h], a2);
            a3 = fmaf(x, fc_w[5 * HH + h], a3);
        }
        #pragma unroll
        for (int o = 16; o; o >>= 1) {
            a0 += __shfl_xor_sync(0xffffffffu, a0, o);
            a1 += __shfl_xor_sync(0xffffffffu, a1, o);
            a2 += __shfl_xor_sync(0xffffffffu, a2, o);
            a3 += __shfl_xor_sync(0xffffffffu, a3, o);
        }
        int w = tid >> 5, lane = tid & 31;
        if (lane == 0) { sm[w * 4 + 0] = a0; sm[w * 4 + 1] = a1; sm[w * 4 + 2] = a2; sm[w * 4 + 3] = a3; }
        __syncthreads();
        if (tid == 0) {
            float s0 = 0.f, s1 = 0.f, s2 = 0.f, s3 = 0.f;
            #pragma unroll
            for (int i = 0; i < 8; i++) { s0 += sm[i*4+0]; s1 += sm[i*4+1]; s2 += sm[i*4+2]; s3 += sm[i*4+3]; }
            s0 += fc_b[0]; s1 += fc_b[1]; s2 += fc_b[4]; s3 += fc_b[5];
            g_heads[t] = s0; g_heads[BL + t] = s1; g_heads[2 * BL + t] = s2; g_heads[3 * BL + t] = s3;
            out[O_FHS + t] = s0; out[O_FHE + t] = s1; out[O_BTS + t] = s2; out[O_BTE + t] = s3;
        }
    }
}

// ================= prepA + span =================
__global__ void k_prepA2(const float* __restrict__ token, const float* __restrict__ f_rel,
                         const float* __restrict__ h_gs) {
    int bid = blockIdx.x;
    if (bid == 336) {
        int w = threadIdx.x >> 5, lane = threadIdx.x & 31;
        if (w >= 8) return;
        int hd = w >> 2, b = w & 3;
        const float* sv = g_heads + hd * 2 * BL + b * LL;
        const float* ev = sv + BL;
        int sidx = 0, has = 0;
        #pragma unroll 1
        for (int c = 0; c < 4; c++) {
            unsigned m = __ballot_sync(0xffffffffu, sv[c * 32 + lane] > 0.f);
            if (m) { sidx = c * 32 + __ffs(m) - 1; has = 1; break; }
        }
        int eidx = sidx;
        #pragma unroll 1
        for (int c = 0; c < 4; c++) {
            int p = c * 32 + lane;
            unsigned m = __ballot_sync(0xffffffffu, (ev[p] > 0.f) && (p >= sidx));
            if (m) { eidx = c * 32 + __ffs(m) - 1; break; }
        }
        if (lane == 0) {
            g_span[hd][b][0] = sidx;
            g_span[hd][b][1] = eidx - sidx + 1;
            g_span[hd][b][2] = has;
        }
        return;
    }
    int idx = bid * 256 + threadIdx.x;
    int g = idx % 96, r = idx / 96;
    int mt = r >> 7, trow = r & 127;
    const float* src = nullptr;
    bool valid = false;
    if (mt < 4)       { src = token + (mt * 128 + trow) * HH; valid = true; }
    else if (mt == 4) { valid = trow < RR; src = f_rel + trow * HH; }
    else if (mt == 5) { valid = trow < RR; src = g_brel + trow * HH; }
    else              { valid = trow < BB; src = h_gs + trow * HH; }
    float xs[8];
    if (valid) {
        float4 v0 = *(const float4*)(src + g * 8);
        float4 v1 = *(const float4*)(src + g * 8 + 4);
        xs[0] = v0.x; xs[1] = v0.y; xs[2] = v0.z; xs[3] = v0.w;
        xs[4] = v1.x; xs[5] = v1.y; xs[6] = v1.z; xs[7] = v1.w;
    } else {
        #pragma unroll
        for (int i = 0; i < 8; i++) xs[i] = 0.f;
    }
    union { unsigned short s[8]; uint4 v; } hi, lo;
    #pragma unroll
    for (int i = 0; i < 8; i++) {
        __nv_bfloat16 h = __float2bfloat16(xs[i]);
        float rem = xs[i] - __bfloat162float(h);
        hi.s[i] = __bfloat16_as_ushort(h);
        lo.s[i] = __bfloat16_as_ushort(__float2bfloat16(rem));
    }
    int kc = g >> 2, kk8 = (g & 3) << 3;
    __nv_bfloat16* bHi = g_Abf + ((mt * 24 + kc) * 2 + 0) * 4096 + trow * 32 + kk8;
    __nv_bfloat16* bLo = g_Abf + ((mt * 24 + kc) * 2 + 1) * 4096 + trow * 32 + kk8;
    *(uint4*)bHi = hi.v;
    *(uint4*)bLo = lo.v;
}

// ---------------- mma.sync bf16 GEMM: 128x64, 2-stage, 3 CTAs/SM ----------------
__global__ void __launch_bounds__(256, 3) k_mma(const float* __restrict__ big_b) {
    extern __shared__ char smem[];
    uint32_t sb = smem_u32(smem);
    int tid = threadIdx.x, wid = tid >> 5, lane = tid & 31;
    int wm = wid & 3, wn = wid >> 2;
    int bid = blockIdx.x;

    int jW, mt, nb, Mvalid; float* outp;
    if (bid < 288) {
        const int widx[6] = {0, 1, 4, 7, 8, 9};
        int j = bid / 48, rem = bid % 48;
        int mb = rem / 12; nb = rem % 12;
        jW = widx[j]; mt = mb; Mvalid = 128;
        outp = g_C + j * BL * HH + mb * 128 * HH;
    } else {
        int s = (bid - 288) / 12; nb = (bid - 288) % 12;
        const int wsel[4] = {2, 5, 3, 6};
        jW = wsel[s];
        if (s == 0)      { mt = 4; Mvalid = RR; outp = g_PRf; }
        else if (s == 1) { mt = 5; Mvalid = RR; outp = g_PRb; }
        else if (s == 2) { mt = 6; Mvalid = BB; outp = g_PGf; }
        else             { mt = 6; Mvalid = BB; outp = g_PGb; }
    }

    const char* gA = (const char*)(g_Abf + (size_t)(mt * 24) * 2 * 4096);
    const char* gB = (const char*)(g_Bbf + (size_t)((jW * 12 + nb) * 24) * 2 * 2048);

    auto stage = [&](int buf, int kc) {
        uint32_t dbase = sb + buf * 30720;
        const char* aSrc = gA + (size_t)kc * 2 * 8192;
        const char* bSrc = gB + (size_t)kc * 2 * 4096;
        #pragma unroll
        for (int ii = 0; ii < 6; ii++) {
            int i = tid + ii * 256;
            if (i < 1024) {
                int row = i >> 3, half = (i >> 2) & 1, c = i & 3;
                cp16(dbase + half * 10240 + row * 80 + c * 16,
                     aSrc + half * 8192 + row * 64 + c * 16);
            } else {
                int j2 = i - 1024;
                int row = j2 >> 3, half = (j2 >> 2) & 1, c = j2 & 3;
                cp16(dbase + 20480 + half * 5120 + row * 80 + c * 16,
                     bSrc + half * 4096 + row * 64 + c * 16);
            }
        }
    };

    float acc[2][4][4];
    #pragma unroll
    for (int a = 0; a < 2; a++)
        #pragma unroll
        for (int b = 0; b < 4; b++)
            #pragma unroll
            for (int c = 0; c < 4; c++) acc[a][b][c] = 0.f;

    uint32_t aOff = (uint32_t)((wm * 32 + (lane & 15)) * 80 + ((lane >> 4) * 8) * 2);
    uint32_t bOff = (uint32_t)((wn * 32 + (((lane >> 4) << 3) | (lane & 7))) * 80 + (lane & 8) * 2);

    stage(0, 0);
    cp_commit();

    for (int kc = 0; kc < 24; kc++) {
        int buf = kc & 1;
        if (kc + 1 < 24) { stage(buf ^ 1, kc + 1); cp_commit(); cp_wait1(); }
        else             { cp_wait0(); }
        __syncthreads();

        uint32_t Ab = sb + buf * 30720;
        uint32_t Bb = Ab + 20480;
        #pragma unroll
        for (int k16 = 0; k16 < 2; k16++) {
            uint32_t ah[2][4], al[2][4], bh[2][4], blr[2][4];
            #pragma unroll
            for (int m = 0; m < 2; m++) {
                uint32_t ad = Ab + aOff + m * (16 * 80) + k16 * 32;
                ldm_x4(ah[m], ad);
                ldm_x4(al[m], ad + 10240);
            }
            #pragma unroll
            for (int nt = 0; nt < 2; nt++) {
                uint32_t bd = Bb + bOff + nt * (16 * 80) + k16 * 32;
                ldm_x4(bh[nt], bd);
                ldm_x4(blr[nt], bd + 5120);
            }
            #pragma unroll
            for (int m = 0; m < 2; m++) {
                #pragma unroll
                for (int j2 = 0; j2 < 4; j2++) {
                    const uint32_t* bhp = &bh[j2 >> 1][(j2 & 1) * 2];
                    const uint32_t* blp = &blr[j2 >> 1][(j2 & 1) * 2];
                    mma_bf16(acc[m][j2], ah[m], bhp);
                    mma_bf16(acc[m][j2], ah[m], blp);
                    mma_bf16(acc[m][j2], al[m], bhp);
                }
            }
        }
        __syncthreads();
    }

    int lr = lane >> 2, lc = (lane & 3) * 2;
    #pragma unroll
    for (int m = 0; m < 2; m++) {
        #pragma unroll
        for (int j2 = 0; j2 < 4; j2++) {
            int col = nb * 64 + wn * 32 + j2 * 8 + lc;
            float2 bv = *(const float2*)(big_b + jW * HH + col);
            int row = wm * 32 + m * 16 + lr;
            if (row < Mvalid) {
                float2 o = make_float2(acc[m][j2][0] + bv.x, acc[m][j2][1] + bv.y);
                *(float2*)(outp + row * HH + col) = o;
            }
            if (row + 8 < Mvalid) {
                float2 o = make_float2(acc[m][j2][2] + bv.x, acc[m][j2][3] + bv.y);
                *(float2*)(outp + (row + 8) * HH + col) = o;
            }
        }
    }
}

// ---------------- attention scores (verified 125us version) ----------------
__global__ void __launch_bounds__(256) k_attn(const float* __restrict__ fc_w) {
    __shared__ __align__(16) float XS[8][HH];
    __shared__ __align__(16) float PRS[8][HH];
    int bid = blockIdx.x;
    int hd = bid / 384; int rem = bid % 384;
    int b = rem / 96; rem %= 96;
    int lt = rem / 6, rt = rem % 6;
    const float* X  = g_C + (size_t)(2 + hd) * BL * HH + (b * LL + lt * 8) * HH;
    const float* PG = (hd ? g_PGb : g_PGf) + b * HH;
    const float* PR = (hd ? g_PRb : g_PRf) + rt * 8 * HH;
    int tid = threadIdx.x;
    for (int i = tid; i < 8 * HH / 4; i += 256) {
        int row = i / 192, c4 = (i % 192) << 2;
        float4 x = *(const float4*)(X + row * HH + c4);
        float4 g = *(const float4*)(PG + c4);
        x.x = __expf(2.0f * (x.x + g.x)); x.y = __expf(2.0f * (x.y + g.y));
        x.z = __expf(2.0f * (x.z + g.z)); x.w = __expf(2.0f * (x.w + g.w));
        *(float4*)&XS[row][c4] = x;
        float4 p = *(const float4*)(PR + row * HH + c4);
        p.x = __expf(2.0f * p.x); p.y = __expf(2.0f * p.y);
        p.z = __expf(2.0f * p.z); p.w = __expf(2.0f * p.w);
        *(float4*)&PRS[row][c4] = p;
    }
    __syncthreads();
    int w = tid >> 5, lane = tid & 31;
    float vw[24], xr[24];
    const float* Vw = fc_w + 8 * HH;
    #pragma unroll
    for (int j = 0; j < 24; j++) {
        int h = lane + (j << 5);
        vw[j] = Vw[h];
        xr[j] = XS[w][h];
    }
    float* vout = g_v + ((hd * BB + b) * LL + lt * 8 + w) * RR + rt * 8;
    #pragma unroll 2
    for (int r = 0; r < 8; r++) {
        float acc = 0.f;
        #pragma unroll
        for (int j = 0; j < 24; j++) {
            float v = xr[j] * PRS[r][lane + (j << 5)];
            float e = 1.0f - __fdividef(2.0f, v + 1.0f);
            acc = fmaf(e, vw[j], acc);
        }
        #pragma unroll
        for (int o = 16; o; o >>= 1) acc += __shfl_xor_sync(0xffffffffu, acc, o);
        if (lane == 0) vout[r] = acc;
    }
}

// ---------------- context with in-kernel softmax ----------------
__global__ void __launch_bounds__(128) k_ctx(const float* __restrict__ token) {
    __shared__ __align__(16) float As[LL][24];
    __shared__ float cmax[24], cinv[24];
    int bid = blockIdx.x;
    int hd = bid / 48; int rem = bid % 48;
    int b = rem / 12; int rem2 = rem % 12;
    int hc = rem2 / 2, rh = rem2 % 2;
    const float* Ag = g_v + (hd * BB + b) * LL * RR + rh * 24;
    int tid = threadIdx.x;
    for (int i = tid; i < LL * 6; i += 128) {
        int row = i / 6, c4 = (i % 6) << 2;
        *(float4*)&As[row][c4] = *(const float4*)(Ag + row * RR + c4);
    }
    __syncthreads();
    if (tid < 96) {
        int col = tid >> 2, q = tid & 3;
        float m = -1e30f;
        for (int l = q; l < LL; l += 4) m = fmaxf(m, As[l][col]);
        m = fmaxf(m, __shfl_xor_sync(0xffffffffu, m, 1));
        m = fmaxf(m, __shfl_xor_sync(0xffffffffu, m, 2));
        float s = 0.f;
        for (int l = q; l < LL; l += 4) s += __expf(As[l][col] - m);
        s += __shfl_xor_sync(0xffffffffu, s, 1);
        s += __shfl_xor_sync(0xffffffffu, s, 2);
        if (q == 0) { cmax[col] = m; cinv[col] = 1.0f / s; }
    }
    __syncthreads();
    for (int i = tid; i < LL * 24; i += 128) {
        int l = i / 24, c = i % 24;
        As[l][c] = __expf(As[l][c] - cmax[c]) * cinv[c];
    }
    __syncthreads();
    int h = hc * 128 + tid;
    const float* tok = token + b * LL * HH + h;
    float acc[24];
    #pragma unroll
    for (int r = 0; r < 24; r++) acc[r] = 0.f;
    for (int l = 0; l < LL; l++) {
        float t = tok[l * HH];
        #pragma unroll
        for (int r = 0; r < 24; r += 4) {
            float4 a = *(const float4*)&As[l][r];
            acc[r + 0] = fmaf(a.x, t, acc[r + 0]);
            acc[r + 1] = fmaf(a.y, t, acc[r + 1]);
            acc[r + 2] = fmaf(a.z, t, acc[r + 2]);
            acc[r + 3] = fmaf(a.w, t, acc[r + 3]);
        }
    }
    float* Cp = g_ctx + ((hd * BB + b) * RR + rh * 24) * HH + h;
    #pragma unroll
    for (int r = 0; r < 24; r++) Cp[r * HH] = acc[r];
}

// ---------------- fused hik | cdot ----------------
__global__ void __launch_bounds__(128) k_hikcdot(const float* __restrict__ token,
                                                 const float* __restrict__ fc_w) {
    int bid = blockIdx.x;
    int tid = threadIdx.x;
    if (bid < 512) {
        int t = bid;
        int b = t >> 7, l = t & 127;
        int sf = g_span[0][b][0], lenf = g_span[0][b][1], hasf = g_span[0][b][2];
        int sb2 = g_span[1][b][0], lenb = g_span[1][b][1], hasb = g_span[1][b][2];
        bool mf = hasf && (l < lenf);
        bool mb2 = hasb && (l < lenb);
        int rf = min(sf + l, LL - 1), rb = min(sb2 + l, LL - 1);
        const float* T0  = g_C + (b * LL + rf) * HH;
        const float* T1  = g_C + 1 * BL * HH + (b * LL + rb) * HH;
        const float* X8  = g_C + 4 * BL * HH + t * HH;
        const float* X9  = g_C + 5 * BL * HH + t * HH;
        const float* tok = token + t * HH;
        const float* w2 = fc_w + 2 * HH; const float* w3 = fc_w + 3 * HH;
        const float* w6 = fc_w + 6 * HH; const float* w7 = fc_w + 7 * HH;
        float a0 = 0.f, a1 = 0.f, a2 = 0.f, a3 = 0.f;
        for (int h = tid; h < HH; h += 128) {
            float vf = (mf ? T0[h] : 0.f) + X8[h] + tok[h];
            float vb = (mb2 ? T1[h] : 0.f) + X9[h] + tok[h];
            a0 = fmaf(vf, w2[h], a0); a1 = fmaf(vf, w3[h], a1);
            a2 = fmaf(vb, w6[h], a2); a3 = fmaf(vb, w7[h], a3);
        }
        #pragma unroll
        for (int o = 16; o; o >>= 1) {
            a0 += __shfl_xor_sync(0xffffffffu, a0, o);
            a1 += __shfl_xor_sync(0xffffffffu, a1, o);
            a2 += __shfl_xor_sync(0xffffffffu, a2, o);
            a3 += __shfl_xor_sync(0xffffffffu, a3, o);
        }
        __shared__ float red[4][4];
        int w = tid >> 5, lane = tid & 31;
        if (lane == 0) { red[w][0] = a0; red[w][1] = a1; red[w][2] = a2; red[w][3] = a3; }
        __syncthreads();
        if (tid == 0) {
            g_dot[t]          = red[0][0] + red[1][0] + red[2][0] + red[3][0];
            g_dot[BL + t]     = red[0][1] + red[1][1] + red[2][1] + red[3][1];
            g_dot[2 * BL + t] = red[0][2] + red[1][2] + red[2][2] + red[3][2];
            g_dot[3 * BL + t] = red[0][3] + red[1][3] + red[2][3] + red[3][3];
        }
    } else {
        int g = (bid - 512) * 4 + (tid >> 5);
        int lane = tid & 31;
        int hd = g / (BB * RR); int rem = g % (BB * RR);
        int b = rem / RR, r = rem % RR;
        const float* C  = g_ctx + ((hd * BB + b) * RR + r) * HH;
        const float* ws = fc_w + (hd ? 6 : 2) * HH;
        const float* we = fc_w + (hd ? 7 : 3) * HH;
        float as = 0.f, ae = 0.f;
        #pragma unroll
        for (int j = 0; j < 24; j++) {
            int h = lane + (j << 5);
            float c = C[h];
            as = fmaf(c, ws[h], as);
            ae = fmaf(c, we[h], ae);
        }
        #pragma unroll
        for (int o = 16; o; o >>= 1) {
            as += __shfl_xor_sync(0xffffffffu, as, o);
            ae += __shfl_xor_sync(0xffffffffu, ae, o);
        }
        if (lane == 0) {
            g_cdot[(hd * 2 + 0) * BB * RR + b * RR + r] = as;
            g_cdot[(hd * 2 + 1) * BB * RR + b * RR + r] = ae;
        }
    }
}

// ---------------- final broadcast logits ----------------
__global__ void k_final(float* __restrict__ out, const float* __restrict__ fc_b) {
    int idx = blockIdx.x * 256 + threadIdx.x;
    int head = idx / (BB * LL * RR), rem = idx % (BB * LL * RR);
    int b = rem / (LL * RR); int rem2 = rem % (LL * RR);
    int l = rem2 / RR, r = rem2 % RR;
    const int ooff[4] = {O_FTS, O_FTE, O_BHS, O_BHE};
    const int bsel[4] = {2, 3, 6, 7};
    float val = g_dot[head * BL + b * LL + l]
              + g_cdot[head * BB * RR + b * RR + r]
              + fc_b[bsel[head]];
    out[ooff[head] + rem] = val;
}

extern "C" void kernel_launch(void* const* d_in, const int* in_sizes, int n_in,
                              void* d_out, int out_size) {
    const float* h_gs       = (const float*)d_in[0];
    const float* token_embs = (const float*)d_in[1];
    const float* f_rel_embs = (const float*)d_in[2];
    const float* b_rel_tr   = (const float*)d_in[3];
    const float* r_proj_w   = (const float*)d_in[4];
    const float* r_proj_b   = (const float*)d_in[5];
    const float* fc_w       = (const float*)d_in[6];
    const float* fc_b       = (const float*)d_in[7];
    const float* big_w      = (const float*)d_in[8];
    const float* big_b      = (const float*)d_in[9];
    float* out = (float*)d_out;

    static int smem_set = 0;
    if (!smem_set) {
        cudaFuncSetAttribute(k_mma, cudaFuncAttributeMaxDynamicSharedMemorySize, MMA_SMEM_TOTAL);
        smem_set = 1;
    }

    k_preB<<<1440, 256>>>(big_w);                                              // slot 0
    k_preR<<<560, 256>>>(b_rel_tr, r_proj_w, r_proj_b, token_embs, fc_w, fc_b, out); // slot 1
    k_prepA2<<<337, 256>>>(token_embs, f_rel_embs, h_gs);                      // slot 2
    k_mma<<<336, 256, MMA_SMEM_TOTAL>>>(big_b);                                // slot 3 (profiled)
    k_attn<<<768, 256>>>(fc_w);
    k_ctx<<<96, 128>>>(token_embs);
    k_hikcdot<<<608, 128>>>(token_embs, fc_w);
    k_final<<<384, 256>>>(out, fc_b);
}

// round 15
// speedup vs baseline: 1.0467x; 1.0003x over previous
#include <cuda_runtime.h>
#include <cuda_bf16.h>
#include <cstdint>

#define BB 4
#define LL 128
#define RR 48
#define HH 768
#define DDIM 100
#define BL 512
#define WSZ (HH*HH)

#define O_FHS 0
#define O_FHE 512
#define O_FTS 1024
#define O_FTE 25600
#define O_BTS 50176
#define O_BTE 50688
#define O_BHS 51200
#define O_BHE 75776

// ---------------- scratch ----------------
__device__ __align__(16) float g_C[6 * BL * HH];
__device__ __align__(16) float g_brel[RR * HH];
__device__ __align__(16) float g_PRf[RR * HH];
__device__ __align__(16) float g_PRb[RR * HH];
__device__ __align__(16) float g_PGf[BB * HH];
__device__ __align__(16) float g_PGb[BB * HH];
__device__ __align__(16) float g_heads[4 * BL];
__device__ int             g_span[2][BB][3];
__device__ __align__(16) float g_v[2 * BB * LL * RR];
__device__ __align__(16) float g_ctx[2 * BB * RR * HH];
__device__ __align__(16) float g_dot[4 * BL];
__device__ __align__(16) float g_cdot[4 * BB * RR];

// prepped bf16 hi/lo data
__device__ __align__(16) __nv_bfloat16 g_Abf[7 * 24 * 2 * 4096];
__device__ __align__(16) __nv_bfloat16 g_Bbf[10 * 12 * 24 * 2 * 2048];

// ================= PTX helpers =================
__device__ __forceinline__ uint32_t smem_u32(const void* p) {
    uint32_t a;
    asm("{ .reg .u64 t; cvta.to.shared.u64 t, %1; cvt.u32.u64 %0, t; }" : "=r"(a) : "l"(p));
    return a;
}
__device__ __forceinline__ void cp16(uint32_t dst, const void* src) {
    asm volatile("cp.async.cg.shared.global [%0], [%1], 16;" :: "r"(dst), "l"(src) : "memory");
}
__device__ __forceinline__ void cp_commit() { asm volatile("cp.async.commit_group;" ::: "memory"); }
__device__ __forceinline__ void cp_wait1()  { asm volatile("cp.async.wait_group 1;" ::: "memory"); }
__device__ __forceinline__ void cp_wait0()  { asm volatile("cp.async.wait_group 0;" ::: "memory"); }
__device__ __forceinline__ void ldm_x4(uint32_t* r, uint32_t addr) {
    asm volatile("ldmatrix.sync.aligned.m8n8.x4.shared.b16 {%0,%1,%2,%3}, [%4];"
                 : "=r"(r[0]), "=r"(r[1]), "=r"(r[2]), "=r"(r[3]) : "r"(addr));
}
__device__ __forceinline__ void mma_bf16(float* d, const uint32_t* a, const uint32_t* b) {
    asm volatile("mma.sync.aligned.m16n8k16.row.col.f32.bf16.bf16.f32 "
                 "{%0,%1,%2,%3}, {%4,%5,%6,%7}, {%8,%9}, {%0,%1,%2,%3};"
                 : "+f"(d[0]), "+f"(d[1]), "+f"(d[2]), "+f"(d[3])
                 : "r"(a[0]), "r"(a[1]), "r"(a[2]), "r"(a[3]), "r"(b[0]), "r"(b[1]));
}

#define MMA_SMEM_TOTAL 61440

// ================= prepB: transpose + split weights (all 10 mats) =================
__global__ void __launch_bounds__(256) k_preB(const float* __restrict__ big_w) {
    __shared__ float sm[64][65];
    int bid = blockIdx.x;
    int tid = threadIdx.x;
    int jW = bid / 144; int rem = bid % 144;
    int nb = rem / 12, kg = rem % 12;
    const float* W = big_w + jW * WSZ + (kg * 64) * HH + nb * 64;
    for (int i = tid; i < 1024; i += 256) {
        int kr = i >> 4, c4 = (i & 15) << 2;
        float4 v = *(const float4*)(W + kr * HH + c4);
        sm[kr][c4 + 0] = v.x; sm[kr][c4 + 1] = v.y; sm[kr][c4 + 2] = v.z; sm[kr][c4 + 3] = v.w;
    }
    __syncthreads();
    for (int i = tid; i < 512; i += 256) {
        int n = i >> 3, g = i & 7;
        union { unsigned short s[8]; uint4 v; } hi, lo;
        #pragma unroll
        for (int j = 0; j < 8; j++) {
            float x = sm[g * 8 + j][n];
            __nv_bfloat16 h = __float2bfloat16(x);
            float rem2 = x - __bfloat162float(h);
            hi.s[j] = __bfloat16_as_ushort(h);
            lo.s[j] = __bfloat16_as_ushort(__float2bfloat16(rem2));
        }
        int kc = kg * 2 + (g >> 2), kk8 = (g & 3) << 3;
        __nv_bfloat16* base = g_Bbf + (size_t)(((jW * 12 + nb) * 24 + kc) * 2) * 2048;
        *(uint4*)(base + n * 32 + kk8) = hi.v;
        *(uint4*)(base + 2048 + n * 32 + kk8) = lo.v;
    }
}

// ================= preR: brel | heads =================
__global__ void __launch_bounds__(256) k_preR(const float* __restrict__ bt,
                                              const float* __restrict__ rW,
                                              const float* __restrict__ rb,
                                              const float* __restrict__ token,
                                              const float* __restrict__ fc_w,
                                              const float* __restrict__ fc_b,
                                              float* __restrict__ out) {
    __shared__ float sm[104];
    int bid = blockIdx.x;
    int tid = threadIdx.x;
    if (bid < 48) {
        int r = bid;
        for (int i = tid; i < DDIM; i += 256) sm[i] = bt[r * DDIM + i];
        __syncthreads();
        for (int c = tid; c < HH; c += 256) {
            float acc = rb[c];
            #pragma unroll 4
            for (int d = 0; d < DDIM; d++) acc = fmaf(sm[d], rW[d * HH + c], acc);
            g_brel[r * HH + c] = acc;
        }
    } else {
        int t = bid - 48;
        const float* tok = token + t * HH;
        float a0 = 0.f, a1 = 0.f, a2 = 0.f, a3 = 0.f;
        for (int h = tid; h < HH; h += 256) {
            float x = tok[h];
            a0 = fmaf(x, fc_w[0 * HH + h], a0);
            a1 = fmaf(x, fc_w[1 * HH + h], a1);
            a2 = fmaf(x, fc_w[4 * HH + h], a2);
            a3 = fmaf(x, fc_w[5 * HH + h], a3);
        }
        #pragma unroll
        for (int o = 16; o; o >>= 1) {
            a0 += __shfl_xor_sync(0xffffffffu, a0, o);
            a1 += __shfl_xor_sync(0xffffffffu, a1, o);
            a2 += __shfl_xor_sync(0xffffffffu, a2, o);
            a3 += __shfl_xor_sync(0xffffffffu, a3, o);
        }
        int w = tid >> 5, lane = tid & 31;
        if (lane == 0) { sm[w * 4 + 0] = a0; sm[w * 4 + 1] = a1; sm[w * 4 + 2] = a2; sm[w * 4 + 3] = a3; }
        __syncthreads();
        if (tid == 0) {
            float s0 = 0.f, s1 = 0.f, s2 = 0.f, s3 = 0.f;
            #pragma unroll
            for (int i = 0; i < 8; i++) { s0 += sm[i*4+0]; s1 += sm[i*4+1]; s2 += sm[i*4+2]; s3 += sm[i*4+3]; }
            s0 += fc_b[0]; s1 += fc_b[1]; s2 += fc_b[4]; s3 += fc_b[5];
            g_heads[t] = s0; g_heads[BL + t] = s1; g_heads[2 * BL + t] = s2; g_heads[3 * BL + t] = s3;
            out[O_FHS + t] = s0; out[O_FHE + t] = s1; out[O_BTS + t] = s2; out[O_BTE + t] = s3;
        }
    }
}

// ================= prepA + span =================
__global__ void k_prepA2(const float* __restrict__ token, const float* __restrict__ f_rel,
                         const float* __restrict__ h_gs) {
    int bid = blockIdx.x;
    if (bid == 336) {
        int w = threadIdx.x >> 5, lane = threadIdx.x & 31;
        if (w >= 8) return;
        int hd = w >> 2, b = w & 3;
        const float* sv = g_heads + hd * 2 * BL + b * LL;
        const float* ev = sv + BL;
        int sidx = 0, has = 0;
        #pragma unroll 1
        for (int c = 0; c < 4; c++) {
            unsigned m = __ballot_sync(0xffffffffu, sv[c * 32 + lane] > 0.f);
            if (m) { sidx = c * 32 + __ffs(m) - 1; has = 1; break; }
        }
        int eidx = sidx;
        #pragma unroll 1
        for (int c = 0; c < 4; c++) {
            int p = c * 32 + lane;
            unsigned m = __ballot_sync(0xffffffffu, (ev[p] > 0.f) && (p >= sidx));
            if (m) { eidx = c * 32 + __ffs(m) - 1; break; }
        }
        if (lane == 0) {
            g_span[hd][b][0] = sidx;
            g_span[hd][b][1] = eidx - sidx + 1;
            g_span[hd][b][2] = has;
        }
        return;
    }
    int idx = bid * 256 + threadIdx.x;
    int g = idx % 96, r = idx / 96;
    int mt = r >> 7, trow = r & 127;
    const float* src = nullptr;
    bool valid = false;
    if (mt < 4)       { src = token + (mt * 128 + trow) * HH; valid = true; }
    else if (mt == 4) { valid = trow < RR; src = f_rel + trow * HH; }
    else if (mt == 5) { valid = trow < RR; src = g_brel + trow * HH; }
    else              { valid = trow < BB; src = h_gs + trow * HH; }
    float xs[8];
    if (valid) {
        float4 v0 = *(const float4*)(src + g * 8);
        float4 v1 = *(const float4*)(src + g * 8 + 4);
        xs[0] = v0.x; xs[1] = v0.y; xs[2] = v0.z; xs[3] = v0.w;
        xs[4] = v1.x; xs[5] = v1.y; xs[6] = v1.z; xs[7] = v1.w;
    } else {
        #pragma unroll
        for (int i = 0; i < 8; i++) xs[i] = 0.f;
    }
    union { unsigned short s[8]; uint4 v; } hi, lo;
    #pragma unroll
    for (int i = 0; i < 8; i++) {
        __nv_bfloat16 h = __float2bfloat16(xs[i]);
        float rem = xs[i] - __bfloat162float(h);
        hi.s[i] = __bfloat16_as_ushort(h);
        lo.s[i] = __bfloat16_as_ushort(__float2bfloat16(rem));
    }
    int kc = g >> 2, kk8 = (g & 3) << 3;
    __nv_bfloat16* bHi = g_Abf + ((mt * 24 + kc) * 2 + 0) * 4096 + trow * 32 + kk8;
    __nv_bfloat16* bLo = g_Abf + ((mt * 24 + kc) * 2 + 1) * 4096 + trow * 32 + kk8;
    *(uint4*)bHi = hi.v;
    *(uint4*)bLo = lo.v;
}

// ---------------- mma.sync bf16 GEMM: 128x64, 2-stage, 3 CTAs/SM + max carveout ----------------
__global__ void __launch_bounds__(256, 3) k_mma(const float* __restrict__ big_b) {
    extern __shared__ char smem[];
    uint32_t sb = smem_u32(smem);
    int tid = threadIdx.x, wid = tid >> 5, lane = tid & 31;
    int wm = wid & 3, wn = wid >> 2;
    int bid = blockIdx.x;

    int jW, mt, nb, Mvalid; float* outp;
    if (bid < 288) {
        const int widx[6] = {0, 1, 4, 7, 8, 9};
        int j = bid / 48, rem = bid % 48;
        int mb = rem / 12; nb = rem % 12;
        jW = widx[j]; mt = mb; Mvalid = 128;
        outp = g_C + j * BL * HH + mb * 128 * HH;
    } else {
        int s = (bid - 288) / 12; nb = (bid - 288) % 12;
        const int wsel[4] = {2, 5, 3, 6};
        jW = wsel[s];
        if (s == 0)      { mt = 4; Mvalid = RR; outp = g_PRf; }
        else if (s == 1) { mt = 5; Mvalid = RR; outp = g_PRb; }
        else if (s == 2) { mt = 6; Mvalid = BB; outp = g_PGf; }
        else             { mt = 6; Mvalid = BB; outp = g_PGb; }
    }

    const char* gA = (const char*)(g_Abf + (size_t)(mt * 24) * 2 * 4096);
    const char* gB = (const char*)(g_Bbf + (size_t)((jW * 12 + nb) * 24) * 2 * 2048);

    auto stage = [&](int buf, int kc) {
        uint32_t dbase = sb + buf * 30720;
        const char* aSrc = gA + (size_t)kc * 2 * 8192;
        const char* bSrc = gB + (size_t)kc * 2 * 4096;
        #pragma unroll
        for (int ii = 0; ii < 6; ii++) {
            int i = tid + ii * 256;
            if (i < 1024) {
                int row = i >> 3, half = (i >> 2) & 1, c = i & 3;
                cp16(dbase + half * 10240 + row * 80 + c * 16,
                     aSrc + half * 8192 + row * 64 + c * 16);
            } else {
                int j2 = i - 1024;
                int row = j2 >> 3, half = (j2 >> 2) & 1, c = j2 & 3;
                cp16(dbase + 20480 + half * 5120 + row * 80 + c * 16,
                     bSrc + half * 4096 + row * 64 + c * 16);
            }
        }
    };

    float acc[2][4][4];
    #pragma unroll
    for (int a = 0; a < 2; a++)
        #pragma unroll
        for (int b = 0; b < 4; b++)
            #pragma unroll
            for (int c = 0; c < 4; c++) acc[a][b][c] = 0.f;

    uint32_t aOff = (uint32_t)((wm * 32 + (lane & 15)) * 80 + ((lane >> 4) * 8) * 2);
    uint32_t bOff = (uint32_t)((wn * 32 + (((lane >> 4) << 3) | (lane & 7))) * 80 + (lane & 8) * 2);

    stage(0, 0);
    cp_commit();

    for (int kc = 0; kc < 24; kc++) {
        int buf = kc & 1;
        if (kc + 1 < 24) { stage(buf ^ 1, kc + 1); cp_commit(); cp_wait1(); }
        else             { cp_wait0(); }
        __syncthreads();

        uint32_t Ab = sb + buf * 30720;
        uint32_t Bb = Ab + 20480;
        #pragma unroll
        for (int k16 = 0; k16 < 2; k16++) {
            uint32_t ah[2][4], al[2][4], bh[2][4], blr[2][4];
            #pragma unroll
            for (int m = 0; m < 2; m++) {
                uint32_t ad = Ab + aOff + m * (16 * 80) + k16 * 32;
                ldm_x4(ah[m], ad);
                ldm_x4(al[m], ad + 10240);
            }
            #pragma unroll
            for (int nt = 0; nt < 2; nt++) {
                uint32_t bd = Bb + bOff + nt * (16 * 80) + k16 * 32;
                ldm_x4(bh[nt], bd);
                ldm_x4(blr[nt], bd + 5120);
            }
            #pragma unroll
            for (int m = 0; m < 2; m++) {
                #pragma unroll
                for (int j2 = 0; j2 < 4; j2++) {
                    const uint32_t* bhp = &bh[j2 >> 1][(j2 & 1) * 2];
                    const uint32_t* blp = &blr[j2 >> 1][(j2 & 1) * 2];
                    mma_bf16(acc[m][j2], ah[m], bhp);
                    mma_bf16(acc[m][j2], ah[m], blp);
                    mma_bf16(acc[m][j2], al[m], bhp);
                }
            }
        }
        __syncthreads();
    }

    int lr = lane >> 2, lc = (lane & 3) * 2;
    #pragma unroll
    for (int m = 0; m < 2; m++) {
        #pragma unroll
        for (int j2 = 0; j2 < 4; j2++) {
            int col = nb * 64 + wn * 32 + j2 * 8 + lc;
            float2 bv = *(const float2*)(big_b + jW * HH + col);
            int row = wm * 32 + m * 16 + lr;
            if (row < Mvalid) {
                float2 o = make_float2(acc[m][j2][0] + bv.x, acc[m][j2][1] + bv.y);
                *(float2*)(outp + row * HH + col) = o;
            }
            if (row + 8 < Mvalid) {
                float2 o = make_float2(acc[m][j2][2] + bv.x, acc[m][j2][3] + bv.y);
                *(float2*)(outp + (row + 8) * HH + col) = o;
            }
        }
    }
}

// ---------------- attention scores (verified 125us version) ----------------
__global__ void __launch_bounds__(256) k_attn(const float* __restrict__ fc_w) {
    __shared__ __align__(16) float XS[8][HH];
    __shared__ __align__(16) float PRS[8][HH];
    int bid = blockIdx.x;
    int hd = bid / 384; int rem = bid % 384;
    int b = rem / 96; rem %= 96;
    int lt = rem / 6, rt = rem % 6;
    const float* X  = g_C + (size_t)(2 + hd) * BL * HH + (b * LL + lt * 8) * HH;
    const float* PG = (hd ? g_PGb : g_PGf) + b * HH;
    const float* PR = (hd ? g_PRb : g_PRf) + rt * 8 * HH;
    int tid = threadIdx.x;
    for (int i = tid; i < 8 * HH / 4; i += 256) {
        int row = i / 192, c4 = (i % 192) << 2;
        float4 x = *(const float4*)(X + row * HH + c4);
        float4 g = *(const float4*)(PG + c4);
        x.x = __expf(2.0f * (x.x + g.x)); x.y = __expf(2.0f * (x.y + g.y));
        x.z = __expf(2.0f * (x.z + g.z)); x.w = __expf(2.0f * (x.w + g.w));
        *(float4*)&XS[row][c4] = x;
        float4 p = *(const float4*)(PR + row * HH + c4);
        p.x = __expf(2.0f * p.x); p.y = __expf(2.0f * p.y);
        p.z = __expf(2.0f * p.z); p.w = __expf(2.0f * p.w);
        *(float4*)&PRS[row][c4] = p;
    }
    __syncthreads();
    int w = tid >> 5, lane = tid & 31;
    float vw[24], xr[24];
    const float* Vw = fc_w + 8 * HH;
    #pragma unroll
    for (int j = 0; j < 24; j++) {
        int h = lane + (j << 5);
        vw[j] = Vw[h];
        xr[j] = XS[w][h];
    }
    float* vout = g_v + ((hd * BB + b) * LL + lt * 8 + w) * RR + rt * 8;
    #pragma unroll 2
    for (int r = 0; r < 8; r++) {
        float acc = 0.f;
        #pragma unroll
        for (int j = 0; j < 24; j++) {
            float v = xr[j] * PRS[r][lane + (j << 5)];
            float e = 1.0f - __fdividef(2.0f, v + 1.0f);
            acc = fmaf(e, vw[j], acc);
        }
        #pragma unroll
        for (int o = 16; o; o >>= 1) acc += __shfl_xor_sync(0xffffffffu, acc, o);
        if (lane == 0) vout[r] = acc;
    }
}

// ---------------- context with in-kernel softmax ----------------
__global__ void __launch_bounds__(128) k_ctx(const float* __restrict__ token) {
    __shared__ __align__(16) float As[LL][24];
    __shared__ float cmax[24], cinv[24];
    int bid = blockIdx.x;
    int hd = bid / 48; int rem = bid % 48;
    int b = rem / 12; int rem2 = rem % 12;
    int hc = rem2 / 2, rh = rem2 % 2;
    const float* Ag = g_v + (hd * BB + b) * LL * RR + rh * 24;
    int tid = threadIdx.x;
    for (int i = tid; i < LL * 6; i += 128) {
        int row = i / 6, c4 = (i % 6) << 2;
        *(float4*)&As[row][c4] = *(const float4*)(Ag + row * RR + c4);
    }
    __syncthreads();
    if (tid < 96) {
        int col = tid >> 2, q = tid & 3;
        float m = -1e30f;
        for (int l = q; l < LL; l += 4) m = fmaxf(m, As[l][col]);
        m = fmaxf(m, __shfl_xor_sync(0xffffffffu, m, 1));
        m = fmaxf(m, __shfl_xor_sync(0xffffffffu, m, 2));
        float s = 0.f;
        for (int l = q; l < LL; l += 4) s += __expf(As[l][col] - m);
        s += __shfl_xor_sync(0xffffffffu, s, 1);
        s += __shfl_xor_sync(0xffffffffu, s, 2);
        if (q == 0) { cmax[col] = m; cinv[col] = 1.0f / s; }
    }
    __syncthreads();
    for (int i = tid; i < LL * 24; i += 128) {
        int l = i / 24, c = i % 24;
        As[l][c] = __expf(As[l][c] - cmax[c]) * cinv[c];
    }
    __syncthreads();
    int h = hc * 128 + tid;
    const float* tok = token + b * LL * HH + h;
    float acc[24];
    #pragma unroll
    for (int r = 0; r < 24; r++) acc[r] = 0.f;
    for (int l = 0; l < LL; l++) {
        float t = tok[l * HH];
        #pragma unroll
        for (int r = 0; r < 24; r += 4) {
            float4 a = *(const float4*)&As[l][r];
            acc[r + 0] = fmaf(a.x, t, acc[r + 0]);
            acc[r + 1] = fmaf(a.y, t, acc[r + 1]);
            acc[r + 2] = fmaf(a.z, t, acc[r + 2]);
            acc[r + 3] = fmaf(a.w, t, acc[r + 3]);
        }
    }
    float* Cp = g_ctx + ((hd * BB + b) * RR + rh * 24) * HH + h;
    #pragma unroll
    for (int r = 0; r < 24; r++) Cp[r * HH] = acc[r];
}

// ---------------- fused hik | cdot ----------------
__global__ void __launch_bounds__(128) k_hikcdot(const float* __restrict__ token,
                                                 const float* __restrict__ fc_w) {
    int bid = blockIdx.x;
    int tid = threadIdx.x;
    if (bid < 512) {
        int t = bid;
        int b = t >> 7, l = t & 127;
        int sf = g_span[0][b][0], lenf = g_span[0][b][1], hasf = g_span[0][b][2];
        int sb2 = g_span[1][b][0], lenb = g_span[1][b][1], hasb = g_span[1][b][2];
        bool mf = hasf && (l < lenf);
        bool mb2 = hasb && (l < lenb);
        int rf = min(sf + l, LL - 1), rb = min(sb2 + l, LL - 1);
        const float* T0  = g_C + (b * LL + rf) * HH;
        const float* T1  = g_C + 1 * BL * HH + (b * LL + rb) * HH;
        const float* X8  = g_C + 4 * BL * HH + t * HH;
        const float* X9  = g_C + 5 * BL * HH + t * HH;
        const float* tok = token + t * HH;
        const float* w2 = fc_w + 2 * HH; const float* w3 = fc_w + 3 * HH;
        const float* w6 = fc_w + 6 * HH; const float* w7 = fc_w + 7 * HH;
        float a0 = 0.f, a1 = 0.f, a2 = 0.f, a3 = 0.f;
        for (int h = tid; h < HH; h += 128) {
            float vf = (mf ? T0[h] : 0.f) + X8[h] + tok[h];
            float vb = (mb2 ? T1[h] : 0.f) + X9[h] + tok[h];
            a0 = fmaf(vf, w2[h], a0); a1 = fmaf(vf, w3[h], a1);
            a2 = fmaf(vb, w6[h], a2); a3 = fmaf(vb, w7[h], a3);
        }
        #pragma unroll
        for (int o = 16; o; o >>= 1) {
            a0 += __shfl_xor_sync(0xffffffffu, a0, o);
            a1 += __shfl_xor_sync(0xffffffffu, a1, o);
            a2 += __shfl_xor_sync(0xffffffffu, a2, o);
            a3 += __shfl_xor_sync(0xffffffffu, a3, o);
        }
        __shared__ float red[4][4];
        int w = tid >> 5, lane = tid & 31;
        if (lane == 0) { red[w][0] = a0; red[w][1] = a1; red[w][2] = a2; red[w][3] = a3; }
        __syncthreads();
        if (tid == 0) {
            g_dot[t]          = red[0][0] + red[1][0] + red[2][0] + red[3][0];
            g_dot[BL + t]     = red[0][1] + red[1][1] + red[2][1] + red[3][1];
            g_dot[2 * BL + t] = red[0][2] + red[1][2] + red[2][2] + red[3][2];
            g_dot[3 * BL + t] = red[0][3] + red[1][3] + red[2][3] + red[3][3];
        }
    } else {
        int g = (bid - 512) * 4 + (tid >> 5);
        int lane = tid & 31;
        int hd = g / (BB * RR); int rem = g % (BB * RR);
        int b = rem / RR, r = rem % RR;
        const float* C  = g_ctx + ((hd * BB + b) * RR + r) * HH;
        const float* ws = fc_w + (hd ? 6 : 2) * HH;
        const float* we = fc_w + (hd ? 7 : 3) * HH;
        float as = 0.f, ae = 0.f;
        #pragma unroll
        for (int j = 0; j < 24; j++) {
            int h = lane + (j << 5);
            float c = C[h];
            as = fmaf(c, ws[h], as);
            ae = fmaf(c, we[h], ae);
        }
        #pragma unroll
        for (int o = 16; o; o >>= 1) {
            as += __shfl_xor_sync(0xffffffffu, as, o);
            ae += __shfl_xor_sync(0xffffffffu, ae, o);
        }
        if (lane == 0) {
            g_cdot[(hd * 2 + 0) * BB * RR + b * RR + r] = as;
            g_cdot[(hd * 2 + 1) * BB * RR + b * RR + r] = ae;
        }
    }
}

// ---------------- final broadcast logits ----------------
__global__ void k_final(float* __restrict__ out, const float* __restrict__ fc_b) {
    int idx = blockIdx.x * 256 + threadIdx.x;
    int head = idx / (BB * LL * RR), rem = idx % (BB * LL * RR);
    int b = rem / (LL * RR); int rem2 = rem % (LL * RR);
    int l = rem2 / RR, r = rem2 % RR;
    const int ooff[4] = {O_FTS, O_FTE, O_BHS, O_BHE};
    const int bsel[4] = {2, 3, 6, 7};
    float val = g_dot[head * BL + b * LL + l]
              + g_cdot[head * BB * RR + b * RR + r]
              + fc_b[bsel[head]];
    out[ooff[head] + rem] = val;
}

extern "C" void kernel_launch(void* const* d_in, const int* in_sizes, int n_in,
                              void* d_out, int out_size) {
    const float* h_gs       = (const float*)d_in[0];
    const float* token_embs = (const float*)d_in[1];
    const float* f_rel_embs = (const float*)d_in[2];
    const float* b_rel_tr   = (const float*)d_in[3];
    const float* r_proj_w   = (const float*)d_in[4];
    const float* r_proj_b   = (const float*)d_in[5];
    const float* fc_w       = (const float*)d_in[6];
    const float* fc_b       = (const float*)d_in[7];
    const float* big_w      = (const float*)d_in[8];
    const float* big_b      = (const float*)d_in[9];
    float* out = (float*)d_out;

    static int attrs_set = 0;
    if (!attrs_set) {
        cudaFuncSetAttribute(k_mma, cudaFuncAttributeMaxDynamicSharedMemorySize, MMA_SMEM_TOTAL);
        cudaFuncSetAttribute(k_mma, cudaFuncAttributePreferredSharedMemoryCarveout, 100);
        attrs_set = 1;
    }

    k_preB<<<1440, 256>>>(big_w);                                              // slot 0
    k_preR<<<560, 256>>>(b_rel_tr, r_proj_w, r_proj_b, token_embs, fc_w, fc_b, out); // slot 1
    k_prepA2<<<337, 256>>>(token_embs, f_rel_embs, h_gs);                      // slot 2
    k_mma<<<336, 256, MMA_SMEM_TOTAL>>>(big_b);                                // slot 3 (profiled)
    k_attn<<<768, 256>>>(fc_w);
    k_ctx<<<96, 128>>>(token_embs);
    k_hikcdot<<<608, 128>>>(token_embs, fc_w);
    k_final<<<384, 256>>>(out, fc_b);
}